// round 8
// baseline (speedup 1.0000x reference)
#include <cuda_runtime.h>
#include <cuda_fp16.h>
#include <math.h>
#include <stdint.h>

// Problem constants
#define NROWS 8192      // B*T
#define TSEQ  2048
#define DM    1024
#define DFF   2048

#define SCALE_QLOG2 0.18033688011112042f   // (1/sqrt(64)) * log2(e)

// ---------------- scratch (static device globals) ---------------------------
__device__ float  g_x   [NROWS * DM];       // f32 residual stream
__device__ __half g_xh  [NROWS * DM];       // half copy of x
__device__ __half g_qkv [NROWS * 3 * DM];   // half qkv (q pre-scaled)
__device__ __half g_attn[NROWS * DM];       // half attention out
__device__ float  g_proj[NROWS * DM];
__device__ __half g_ff1 [NROWS * DFF];      // half, post-relu
__device__ float  g_ff2 [NROWS * DM];

#define WT_QKV 0
#define WT_O   (3072 * 1024)
#define WT_W1  (WT_O + 1024 * 1024)
#define WT_W2  (WT_W1 + 2048 * 1024)
#define WT_LAYER (WT_W2 + 1024 * 2048)
__device__ __half g_wt[6 * WT_LAYER];       // transposed half weights [N][K]
__device__ float  g_bqs[6 * 3072];          // scaled qkv bias

// ---------------- PTX helpers ------------------------------------------------
__device__ __forceinline__ float ex2(float x) {
    float y; asm("ex2.approx.f32 %0, %1;" : "=f"(y) : "f"(x)); return y;
}
__device__ __forceinline__ uint32_t pack_half2(float lo, float hi) {
    uint32_t u;
    asm("cvt.rn.f16x2.f32 %0, %1, %2;" : "=r"(u) : "f"(hi), "f"(lo));
    return u;
}
__device__ __forceinline__ void mma_f16(
    float& d0, float& d1, float& d2, float& d3,
    uint32_t a0, uint32_t a1, uint32_t a2, uint32_t a3,
    uint32_t b0, uint32_t b1)
{
    asm volatile(
        "mma.sync.aligned.m16n8k16.row.col.f32.f16.f16.f32 "
        "{%0,%1,%2,%3},{%4,%5,%6,%7},{%8,%9},{%0,%1,%2,%3};\n"
        : "+f"(d0), "+f"(d1), "+f"(d2), "+f"(d3)
        : "r"(a0), "r"(a1), "r"(a2), "r"(a3), "r"(b0), "r"(b1));
}
__device__ __forceinline__ uint32_t smem_u32(const void* p) {
    uint32_t a;
    asm("{ .reg .u64 t; cvta.to.shared.u64 t, %1; cvt.u32.u64 %0, t; }"
        : "=r"(a) : "l"(p));
    return a;
}
#define LDSM4(R0, R1, R2, R3, ADDR) \
    asm volatile("ldmatrix.sync.aligned.m8n8.x4.shared.b16 {%0,%1,%2,%3}, [%4];" \
        : "=r"(R0), "=r"(R1), "=r"(R2), "=r"(R3) : "r"(ADDR))
#define LDSM4T(R0, R1, R2, R3, ADDR) \
    asm volatile("ldmatrix.sync.aligned.m8n8.x4.trans.shared.b16 {%0,%1,%2,%3}, [%4];" \
        : "=r"(R0), "=r"(R1), "=r"(R2), "=r"(R3) : "r"(ADDR))
#define CPA16(dst, src) \
    asm volatile("cp.async.ca.shared.global [%0], [%1], 16;" \
        :: "r"(dst), "l"(src) : "memory")
#define CPA_COMMIT() asm volatile("cp.async.commit_group;" ::: "memory")
#define CPA_WAIT2()  asm volatile("cp.async.wait_group 2;" ::: "memory")
#define CPA_WAIT3()  asm volatile("cp.async.wait_group 3;" ::: "memory")

// ---------------- merged weight prep: all transposes in ONE launch ----------
__device__ __forceinline__ void transpose_tile(
    const float* __restrict__ W, __half* __restrict__ WT, int K, int N,
    int bx, int by, int scale_rows, float scale)
{
    __shared__ float t[32][33];
    int tx = threadIdx.x & 31, ty = threadIdx.x >> 5;
    #pragma unroll
    for (int i = 0; i < 4; i++)
        t[ty + i * 8][tx] = W[(size_t)(by * 32 + ty + i * 8) * N + bx * 32 + tx];
    __syncthreads();
    #pragma unroll
    for (int i = 0; i < 4; i++) {
        int n = bx * 32 + ty + i * 8;
        float v = t[tx][ty + i * 8];
        if (n < scale_rows) v *= scale;
        WT[(size_t)n * K + by * 32 + tx] = __float2half_rn(v);
    }
}

__global__ __launch_bounds__(256) void prep_weights(
    const float* __restrict__ Wqkv, const float* __restrict__ Wo,
    const float* __restrict__ W1,   const float* __restrict__ W2,
    __half* __restrict__ wt)
{
    int l = blockIdx.z;
    __half* wl = wt + (size_t)l * WT_LAYER;
    int bid = blockIdx.x;
    if (bid < 3072) {                                   // QKV: 96 x 32 tiles
        transpose_tile(Wqkv + (size_t)l * 1024 * 3072, wl + WT_QKV,
                       1024, 3072, bid % 96, bid / 96, 1024, SCALE_QLOG2);
    } else if (bid < 4096) {                            // O: 32 x 32
        bid -= 3072;
        transpose_tile(Wo + (size_t)l * 1024 * 1024, wl + WT_O,
                       1024, 1024, bid % 32, bid / 32, 0, 1.f);
    } else if (bid < 6144) {                            // W1: 64 x 32
        bid -= 4096;
        transpose_tile(W1 + (size_t)l * 1024 * 2048, wl + WT_W1,
                       1024, 2048, bid % 64, bid / 64, 0, 1.f);
    } else {                                            // W2: 32 x 64
        bid -= 6144;
        transpose_tile(W2 + (size_t)l * 2048 * 1024, wl + WT_W2,
                       2048, 1024, bid % 32, bid / 32, 0, 1.f);
    }
}

// ---------------- embedding + PE + qkv bias scaling (one launch) -----------
__global__ __launch_bounds__(256) void embed_bias_kernel(
    const int* __restrict__ tokens, const float* __restrict__ emb,
    float* __restrict__ x, __half* __restrict__ xh,
    const float* __restrict__ bqkv, float* __restrict__ bqs)
{
    if (blockIdx.x >= NROWS) {   // bias scaling: 72 blocks cover 6*3072
        int i = (blockIdx.x - NROWS) * 256 + threadIdx.x;
        float v = bqkv[i];
        bqs[i] = ((i % 3072) < 1024) ? v * SCALE_QLOG2 : v;
        return;
    }
    int row = blockIdx.x;
    int tok = tokens[row];
    float tpos = (float)(row & (TSEQ - 1));
    int c = threadIdx.x * 4;
    float4 e = *(const float4*)(emb + (size_t)tok * DM + c);
    float o[4] = {e.x, e.y, e.z, e.w};
    #pragma unroll
    for (int q = 0; q < 4; q++) {
        int cc = c + q;
        float fi = (float)(cc & ~1);
        float ang = tpos * __expf(fi * -0.00899447301950799f);
        o[q] += (cc & 1) ? cosf(ang) : sinf(ang);
    }
    float4 r; r.x = o[0]; r.y = o[1]; r.z = o[2]; r.w = o[3];
    *(float4*)(x + (size_t)row * DM + c) = r;
    uint2 u; u.x = pack_half2(o[0], o[1]); u.y = pack_half2(o[2], o[3]);
    *(uint2*)(xh + (size_t)row * DM + c) = u;
}

// ---------------- fp16 HMMA GEMM: 4-ring, conditional prefetch --------------
#define GAST 72
#define A_STAGE_H (128 * GAST)
#define B_STAGE_H (256 * GAST)
#define STAGE_H (A_STAGE_H + B_STAGE_H)
#define GEMM_SMEM (4 * STAGE_H * 2)

__global__ __launch_bounds__(256, 1) void gemm_f16(
    const __half* __restrict__ A, const __half* __restrict__ B,
    const float* __restrict__ bias, void* __restrict__ Cout,
    int M, int N, int K, int mode)
{
    extern __shared__ __half sh[];
    uint32_t sbase = smem_u32(sh);
    int tid = threadIdx.x, w = tid >> 5, lane = tid & 31;
    int g = lane >> 2, t = lane & 3;
    int wm = w >> 2, wn = w & 3;
    int rowBase = blockIdx.y * 128, colBase = blockIdx.x * 256;

    float acc[4][8][4];
    #pragma unroll
    for (int i = 0; i < 4; i++)
        #pragma unroll
        for (int j = 0; j < 8; j++)
            #pragma unroll
            for (int r = 0; r < 4; r++) acc[i][j][r] = 0.f;

    const int nc = K >> 6;

    #pragma unroll
    for (int c0 = 0; c0 < 3; ++c0) {
        uint32_t st = sbase + (uint32_t)c0 * (STAGE_H * 2);
        int kb = c0 * 64;
        #pragma unroll
        for (int it = 0; it < 4; ++it) {
            int p = tid + it * 256;
            int r = p >> 3, c8 = (p & 7) * 8;
            CPA16(st + (uint32_t)(r * GAST + c8) * 2u,
                  A + (size_t)(rowBase + r) * K + kb + c8);
        }
        #pragma unroll
        for (int it = 0; it < 8; ++it) {
            int p = tid + it * 256;
            int r = p >> 3, c8 = (p & 7) * 8;
            CPA16(st + (uint32_t)(A_STAGE_H + r * GAST + c8) * 2u,
                  B + (size_t)(colBase + r) * K + kb + c8);
        }
        CPA_COMMIT();
    }

    int lm = lane & 15, lh8 = ((lane >> 4) & 1) * 8;
    int bn = (lane & 7) + (((lane >> 4) & 1) * 8);
    int bk8 = ((lane >> 3) & 1) * 8;

    for (int c = 0; c < nc; ++c) {
        CPA_WAIT2();
        __syncthreads();

        // conditional prefetch; commit ALWAYS (empty groups keep counts sound)
        int cn = c + 3;
        if (cn < nc) {
            uint32_t s2 = sbase + (uint32_t)(cn & 3) * (STAGE_H * 2);
            int kb = cn * 64;
            #pragma unroll
            for (int it = 0; it < 4; ++it) {
                int p = tid + it * 256;
                int r = p >> 3, c8 = (p & 7) * 8;
                CPA16(s2 + (uint32_t)(r * GAST + c8) * 2u,
                      A + (size_t)(rowBase + r) * K + kb + c8);
            }
            #pragma unroll
            for (int it = 0; it < 8; ++it) {
                int p = tid + it * 256;
                int r = p >> 3, c8 = (p & 7) * 8;
                CPA16(s2 + (uint32_t)(A_STAGE_H + r * GAST + c8) * 2u,
                      B + (size_t)(colBase + r) * K + kb + c8);
            }
        }
        CPA_COMMIT();

        uint32_t st = sbase + (uint32_t)(c & 3) * (STAGE_H * 2);
        uint32_t aB = st, bB = st + A_STAGE_H * 2;

        #pragma unroll
        for (int ks = 0; ks < 4; ++ks) {
            uint32_t af[4][4], bf[8][2];
            #pragma unroll
            for (int mt = 0; mt < 4; ++mt) {
                int m0 = wm * 64 + mt * 16;
                uint32_t ad = aB + (uint32_t)((m0 + lm) * GAST + ks * 16 + lh8) * 2u;
                LDSM4(af[mt][0], af[mt][1], af[mt][2], af[mt][3], ad);
            }
            #pragma unroll
            for (int j = 0; j < 4; ++j) {
                int n0 = wn * 64 + j * 16;
                uint32_t bd = bB + (uint32_t)((n0 + bn) * GAST + ks * 16 + bk8) * 2u;
                LDSM4(bf[2*j][0], bf[2*j][1], bf[2*j+1][0], bf[2*j+1][1], bd);
            }
            #pragma unroll
            for (int mt = 0; mt < 4; ++mt)
                #pragma unroll
                for (int nt = 0; nt < 8; ++nt)
                    mma_f16(acc[mt][nt][0], acc[mt][nt][1],
                            acc[mt][nt][2], acc[mt][nt][3],
                            af[mt][0], af[mt][1], af[mt][2], af[mt][3],
                            bf[nt][0], bf[nt][1]);
        }
    }

    int relu = mode & 1, hout = mode & 2;
    #pragma unroll
    for (int mt = 0; mt < 4; ++mt) {
        int r0g = rowBase + wm * 64 + mt * 16 + g;
        #pragma unroll
        for (int nt = 0; nt < 8; ++nt) {
            int cc = colBase + wn * 64 + nt * 8 + 2 * t;
            float b0 = bias[cc], b1 = bias[cc + 1];
            float v0 = acc[mt][nt][0] + b0, v1 = acc[mt][nt][1] + b1;
            float v2 = acc[mt][nt][2] + b0, v3 = acc[mt][nt][3] + b1;
            if (relu) {
                v0 = fmaxf(v0, 0.f); v1 = fmaxf(v1, 0.f);
                v2 = fmaxf(v2, 0.f); v3 = fmaxf(v3, 0.f);
            }
            if (hout) {
                *(uint32_t*)((__half*)Cout + (size_t)r0g * N + cc) = pack_half2(v0, v1);
                *(uint32_t*)((__half*)Cout + (size_t)(r0g + 8) * N + cc) = pack_half2(v2, v3);
            } else {
                float2 p0; p0.x = v0; p0.y = v1;
                float2 p1; p1.x = v2; p1.y = v3;
                *(float2*)((float*)Cout + (size_t)r0g * N + cc) = p0;
                *(float2*)((float*)Cout + (size_t)(r0g + 8) * N + cc) = p1;
            }
        }
    }
}

// ---------------- fp16 flash attention: FA2 register-P, low-reg variant -----
#define FQST 72
#define FKST 72
#define FQ_OFF 0
#define FKBUF  (64 * FKST)
#define FK_OFF (128 * FQST)
#define FV_OFF (FK_OFF + 4 * FKBUF)
#define ATT_SMEM ((FV_OFF + 4 * FKBUF) * 2)
#define NTILE (TSEQ / 64)

__global__ __launch_bounds__(256, 2) void flash_f16(
    const __half* __restrict__ qkv, __half* __restrict__ attn)
{
    extern __shared__ __half sf[];
    uint32_t sbase = smem_u32(sf);
    int tid = threadIdx.x, w = tid >> 5, lane = tid & 31;
    int g = lane >> 2, t = lane & 3;
    int h = blockIdx.y, b = blockIdx.z;
    int btQ = b * TSEQ + blockIdx.x * 128;
    int rl0 = w * 16;
    int lm = lane & 15, lh8 = ((lane >> 4) & 1) * 8;
    int bn = (lane & 7) + (((lane >> 4) & 1) * 8);
    int bk8 = ((lane >> 3) & 1) * 8;

    // Q prologue (group 0)
    #pragma unroll
    for (int it = 0; it < 4; ++it) {
        int p = tid + it * 256;
        int r = p >> 3, c8 = (p & 7) * 8;
        CPA16(sbase + (uint32_t)(FQ_OFF + r * FQST + c8) * 2u,
              qkv + (size_t)(btQ + r) * 3072 + h * 64 + c8);
    }
    CPA_COMMIT();

    // K/V tiles 0..2 (groups 1..3)
    #pragma unroll
    for (int i0 = 0; i0 < 3; ++i0) {
        #pragma unroll
        for (int it = 0; it < 2; ++it) {
            int p = tid + it * 256;
            int r = p >> 3, c8 = (p & 7) * 8;
            const __half* src = qkv + (size_t)(b * TSEQ + i0 * 64 + r) * 3072 + h * 64;
            CPA16(sbase + (uint32_t)(FK_OFF + i0 * FKBUF + r * FKST + c8) * 2u,
                  src + 1024 + c8);
            CPA16(sbase + (uint32_t)(FV_OFF + i0 * FKBUF + r * FKST + c8) * 2u,
                  src + 2048 + c8);
        }
        CPA_COMMIT();
    }

    CPA_WAIT3();
    __syncthreads();   // Q loaded cooperatively across warps

    float o[8][4];
    #pragma unroll
    for (int d = 0; d < 8; d++)
        #pragma unroll
        for (int r = 0; r < 4; r++) o[d][r] = 0.f;
    float m0 = -1e30f, m1 = -1e30f, l0 = 0.f, l1 = 0.f;

    for (int c = 0; c < NTILE; ++c) {
        CPA_WAIT2();
        __syncthreads();

        int cn = c + 3;
        if (cn < NTILE) {
            int rb = cn & 3;
            #pragma unroll
            for (int it = 0; it < 2; ++it) {
                int p = tid + it * 256;
                int r = p >> 3, c8 = (p & 7) * 8;
                const __half* src = qkv + (size_t)(b * TSEQ + cn * 64 + r) * 3072 + h * 64;
                CPA16(sbase + (uint32_t)(FK_OFF + rb * FKBUF + r * FKST + c8) * 2u,
                      src + 1024 + c8);
                CPA16(sbase + (uint32_t)(FV_OFF + rb * FKBUF + r * FKST + c8) * 2u,
                      src + 2048 + c8);
            }
        }
        CPA_COMMIT();

        uint32_t kB = sbase + (uint32_t)(FK_OFF + (c & 3) * FKBUF) * 2u;
        uint32_t vB = sbase + (uint32_t)(FV_OFF + (c & 3) * FKBUF) * 2u;

        // S = Q K^T; Q frags re-loaded per tile (keeps regs under the 2-CTA cap)
        float s[8][4];
        #pragma unroll
        for (int nt = 0; nt < 8; ++nt)
            s[nt][0] = s[nt][1] = s[nt][2] = s[nt][3] = 0.f;
        #pragma unroll
        for (int ks = 0; ks < 4; ++ks) {
            uint32_t qa[4];
            uint32_t qd = sbase + (uint32_t)(FQ_OFF + (rl0 + lm) * FQST + ks * 16 + lh8) * 2u;
            LDSM4(qa[0], qa[1], qa[2], qa[3], qd);
            uint32_t kf[8][2];
            #pragma unroll
            for (int j = 0; j < 4; ++j) {
                uint32_t kd = kB + (uint32_t)((j * 16 + bn) * FKST + ks * 16 + bk8) * 2u;
                LDSM4(kf[2*j][0], kf[2*j][1], kf[2*j+1][0], kf[2*j+1][1], kd);
            }
            #pragma unroll
            for (int nt = 0; nt < 8; ++nt)
                mma_f16(s[nt][0], s[nt][1], s[nt][2], s[nt][3],
                        qa[0], qa[1], qa[2], qa[3], kf[nt][0], kf[nt][1]);
        }

        // online softmax (base-2); P packed straight into mma A-fragments
        float mx0 = -1e30f, mx1 = -1e30f;
        #pragma unroll
        for (int nt = 0; nt < 8; ++nt) {
            mx0 = fmaxf(mx0, fmaxf(s[nt][0], s[nt][1]));
            mx1 = fmaxf(mx1, fmaxf(s[nt][2], s[nt][3]));
        }
        mx0 = fmaxf(mx0, __shfl_xor_sync(0xffffffffu, mx0, 1));
        mx0 = fmaxf(mx0, __shfl_xor_sync(0xffffffffu, mx0, 2));
        mx1 = fmaxf(mx1, __shfl_xor_sync(0xffffffffu, mx1, 1));
        mx1 = fmaxf(mx1, __shfl_xor_sync(0xffffffffu, mx1, 2));
        float nm0 = fmaxf(m0, mx0), nm1 = fmaxf(m1, mx1);
        float al0 = ex2(m0 - nm0), al1 = ex2(m1 - nm1);
        m0 = nm0; m1 = nm1;

        float rs0 = 0.f, rs1 = 0.f;
        uint32_t pa[4][4];
        #pragma unroll
        for (int j = 0; j < 4; ++j) {
            float p00 = ex2(s[2*j][0] - m0),   p01 = ex2(s[2*j][1] - m0);
            float p02 = ex2(s[2*j][2] - m1),   p03 = ex2(s[2*j][3] - m1);
            float p10 = ex2(s[2*j+1][0] - m0), p11 = ex2(s[2*j+1][1] - m0);
            float p12 = ex2(s[2*j+1][2] - m1), p13 = ex2(s[2*j+1][3] - m1);
            rs0 += p00 + p01 + p10 + p11;
            rs1 += p02 + p03 + p12 + p13;
            pa[j][0] = pack_half2(p00, p01);
            pa[j][1] = pack_half2(p02, p03);
            pa[j][2] = pack_half2(p10, p11);
            pa[j][3] = pack_half2(p12, p13);
        }
        rs0 += __shfl_xor_sync(0xffffffffu, rs0, 1);
        rs0 += __shfl_xor_sync(0xffffffffu, rs0, 2);
        rs1 += __shfl_xor_sync(0xffffffffu, rs1, 1);
        rs1 += __shfl_xor_sync(0xffffffffu, rs1, 2);
        l0 = l0 * al0 + rs0;
        l1 = l1 * al1 + rs1;
        #pragma unroll
        for (int d = 0; d < 8; d++) {
            o[d][0] *= al0; o[d][1] *= al0;
            o[d][2] *= al1; o[d][3] *= al1;
        }

        // O += P @ V
        #pragma unroll
        for (int ks = 0; ks < 4; ++ks) {
            uint32_t vf[8][2];
            #pragma unroll
            for (int j = 0; j < 4; ++j) {
                uint32_t vd = vB + (uint32_t)((ks * 16 + lm) * FKST + j * 16 + lh8) * 2u;
                LDSM4T(vf[2*j][0], vf[2*j][1], vf[2*j+1][0], vf[2*j+1][1], vd);
            }
            #pragma unroll
            for (int dt = 0; dt < 8; ++dt)
                mma_f16(o[dt][0], o[dt][1], o[dt][2], o[dt][3],
                        pa[ks][0], pa[ks][1], pa[ks][2], pa[ks][3],
                        vf[dt][0], vf[dt][1]);
        }
    }

    float i0 = 1.f / l0, i1 = 1.f / l1;
    #pragma unroll
    for (int dt = 0; dt < 8; ++dt) {
        size_t base = (size_t)(btQ + rl0 + g) * DM + h * 64 + dt * 8 + 2 * t;
        *(uint32_t*)(attn + base) = pack_half2(o[dt][0] * i0, o[dt][1] * i0);
        *(uint32_t*)(attn + base + 8 * DM) = pack_half2(o[dt][2] * i1, o[dt][3] * i1);
    }
}

// ---------------- fused residual add + LayerNorm (f32 + half outputs) ------
__global__ __launch_bounds__(256) void add_ln_kernel(
    const float* __restrict__ x, const float* __restrict__ y,
    const float* __restrict__ g, const float* __restrict__ b,
    float* __restrict__ outp, __half* __restrict__ oh)
{
    __shared__ float red[8];
    __shared__ float bc;
    int row = blockIdx.x, tid = threadIdx.x;
    int lane = tid & 31, warp = tid >> 5;

    float4 xv = *(const float4*)(x + (size_t)row * DM + tid * 4);
    float4 yv = *(const float4*)(y + (size_t)row * DM + tid * 4);
    float v0 = xv.x + yv.x, v1 = xv.y + yv.y, v2 = xv.z + yv.z, v3 = xv.w + yv.w;

    float s = v0 + v1 + v2 + v3;
    #pragma unroll
    for (int off = 16; off > 0; off >>= 1) s += __shfl_xor_sync(0xffffffffu, s, off);
    if (lane == 0) red[warp] = s;
    __syncthreads();
    if (tid < 8) {
        float tt = red[tid];
        #pragma unroll
        for (int off = 4; off > 0; off >>= 1) tt += __shfl_xor_sync(0xffu, tt, off);
        if (tid == 0) bc = tt;
    }
    __syncthreads();
    float mean = bc * (1.f / (float)DM);

    float d0 = v0 - mean, d1 = v1 - mean, d2 = v2 - mean, d3 = v3 - mean;
    float sq = d0 * d0 + d1 * d1 + d2 * d2 + d3 * d3;
    #pragma unroll
    for (int off = 16; off > 0; off >>= 1) sq += __shfl_xor_sync(0xffffffffu, sq, off);
    __syncthreads();
    if (lane == 0) red[warp] = sq;
    __syncthreads();
    if (tid < 8) {
        float tt = red[tid];
        #pragma unroll
        for (int off = 4; off > 0; off >>= 1) tt += __shfl_xor_sync(0xffu, tt, off);
        if (tid == 0) bc = tt;
    }
    __syncthreads();
    float rstd = rsqrtf(bc * (1.f / (float)DM) + 1e-5f);

    float4 gv = *(const float4*)(g + tid * 4);
    float4 bv = *(const float4*)(b + tid * 4);
    float4 ov;
    ov.x = d0 * rstd * gv.x + bv.x;
    ov.y = d1 * rstd * gv.y + bv.y;
    ov.z = d2 * rstd * gv.z + bv.z;
    ov.w = d3 * rstd * gv.w + bv.w;
    *(float4*)(outp + (size_t)row * DM + tid * 4) = ov;
    uint2 u; u.x = pack_half2(ov.x, ov.y); u.y = pack_half2(ov.z, ov.w);
    *(uint2*)(oh + (size_t)row * DM + tid * 4) = u;
}

// ---------------- launcher ---------------------------------------------------
extern "C" void kernel_launch(void* const* d_in, const int* in_sizes, int n_in,
                              void* d_out, int out_size)
{
    (void)in_sizes; (void)n_in; (void)out_size;
    const int*   tokens = (const int*)  d_in[0];
    const float* emb  = (const float*)d_in[1];
    const float* Wqkv = (const float*)d_in[2];
    const float* bqkv = (const float*)d_in[3];
    const float* Wo   = (const float*)d_in[4];
    const float* bo   = (const float*)d_in[5];
    const float* g1   = (const float*)d_in[6];
    const float* be1  = (const float*)d_in[7];
    const float* W1   = (const float*)d_in[8];
    const float* bf1  = (const float*)d_in[9];
    const float* W2   = (const float*)d_in[10];
    const float* bf2  = (const float*)d_in[11];
    const float* g2   = (const float*)d_in[12];
    const float* be2  = (const float*)d_in[13];
    float* outp = (float*)d_out;

    float *x, *proj, *ff2, *bqs;
    __half *xh, *qkv, *attn, *ff1, *wt;
    cudaGetSymbolAddress((void**)&x,    g_x);
    cudaGetSymbolAddress((void**)&xh,   g_xh);
    cudaGetSymbolAddress((void**)&qkv,  g_qkv);
    cudaGetSymbolAddress((void**)&attn, g_attn);
    cudaGetSymbolAddress((void**)&proj, g_proj);
    cudaGetSymbolAddress((void**)&ff1,  g_ff1);
    cudaGetSymbolAddress((void**)&ff2,  g_ff2);
    cudaGetSymbolAddress((void**)&wt,   g_wt);
    cudaGetSymbolAddress((void**)&bqs,  g_bqs);

    cudaFuncSetAttribute(gemm_f16, cudaFuncAttributeMaxDynamicSharedMemorySize,
                         GEMM_SMEM);
    cudaFuncSetAttribute(flash_f16, cudaFuncAttributeMaxDynamicSharedMemorySize,
                         ATT_SMEM);

    // prep: 2 launches -> hot kernels start at launch index 2
    prep_weights<<<dim3(8192, 1, 6), 256>>>(Wqkv, Wo, W1, W2, wt);          // 0
    embed_bias_kernel<<<NROWS + 72, 256>>>(tokens, emb, x, xh, bqkv, bqs);  // 1

    for (int l = 0; l < 6; ++l) {
        __half* wl = wt + (size_t)l * WT_LAYER;

        gemm_f16<<<dim3(3072 / 256, NROWS / 128), 256, GEMM_SMEM>>>(
            xh, wl + WT_QKV, bqs + (size_t)l * 3072, qkv,
            NROWS, 3 * DM, DM, 2);

        flash_f16<<<dim3(TSEQ / 128, 16, 4), 256, ATT_SMEM>>>(qkv, attn);

        gemm_f16<<<dim3(1024 / 256, NROWS / 128), 256, GEMM_SMEM>>>(
            attn, wl + WT_O, bo + (size_t)l * DM, proj,
            NROWS, DM, DM, 0);

        add_ln_kernel<<<NROWS, 256>>>(x, proj, g1 + (size_t)l * DM,
                                      be1 + (size_t)l * DM, x, xh);

        gemm_f16<<<dim3(2048 / 256, NROWS / 128), 256, GEMM_SMEM>>>(
            xh, wl + WT_W1, bf1 + (size_t)l * DFF, ff1,
            NROWS, DFF, DM, 3);

        gemm_f16<<<dim3(1024 / 256, NROWS / 128), 256, GEMM_SMEM>>>(
            ff1, wl + WT_W2, bf2 + (size_t)l * DM, ff2,
            NROWS, DM, DFF, 0);

        add_ln_kernel<<<NROWS, 256>>>(x, ff2, g2 + (size_t)l * DM,
                                      be2 + (size_t)l * DM,
                                      (l == 5) ? outp : x, xh);
    }
}

// round 9
// speedup vs baseline: 1.0760x; 1.0760x over previous
#include <cuda_runtime.h>
#include <cuda_fp16.h>
#include <math.h>
#include <stdint.h>

// Problem constants
#define NROWS 8192      // B*T
#define TSEQ  2048
#define DM    1024
#define DFF   2048

#define SCALE_QLOG2 0.18033688011112042f   // (1/sqrt(64)) * log2(e)

// ---------------- scratch (static device globals) ---------------------------
__device__ float  g_x   [NROWS * DM];
__device__ __half g_xh  [NROWS * DM];
__device__ __half g_qkv [NROWS * 3 * DM];
__device__ __half g_attn[NROWS * DM];
__device__ float  g_proj[NROWS * DM];
__device__ __half g_ff1 [NROWS * DFF];
__device__ float  g_ff2 [NROWS * DM];

#define WT_QKV 0
#define WT_O   (3072 * 1024)
#define WT_W1  (WT_O + 1024 * 1024)
#define WT_W2  (WT_W1 + 2048 * 1024)
#define WT_LAYER (WT_W2 + 1024 * 2048)
__device__ __half g_wt[6 * WT_LAYER];
__device__ float  g_bqs[6 * 3072];

// ---------------- PTX helpers ------------------------------------------------
__device__ __forceinline__ float ex2(float x) {
    float y; asm("ex2.approx.f32 %0, %1;" : "=f"(y) : "f"(x)); return y;
}
__device__ __forceinline__ uint32_t pack_half2(float lo, float hi) {
    uint32_t u;
    asm("cvt.rn.f16x2.f32 %0, %1, %2;" : "=r"(u) : "f"(hi), "f"(lo));
    return u;
}
__device__ __forceinline__ void mma_f16(
    float& d0, float& d1, float& d2, float& d3,
    uint32_t a0, uint32_t a1, uint32_t a2, uint32_t a3,
    uint32_t b0, uint32_t b1)
{
    asm volatile(
        "mma.sync.aligned.m16n8k16.row.col.f32.f16.f16.f32 "
        "{%0,%1,%2,%3},{%4,%5,%6,%7},{%8,%9},{%0,%1,%2,%3};\n"
        : "+f"(d0), "+f"(d1), "+f"(d2), "+f"(d3)
        : "r"(a0), "r"(a1), "r"(a2), "r"(a3), "r"(b0), "r"(b1));
}
__device__ __forceinline__ uint32_t smem_u32(const void* p) {
    uint32_t a;
    asm("{ .reg .u64 t; cvta.to.shared.u64 t, %1; cvt.u32.u64 %0, t; }"
        : "=r"(a) : "l"(p));
    return a;
}
#define LDSM4(R0, R1, R2, R3, ADDR) \
    asm volatile("ldmatrix.sync.aligned.m8n8.x4.shared.b16 {%0,%1,%2,%3}, [%4];" \
        : "=r"(R0), "=r"(R1), "=r"(R2), "=r"(R3) : "r"(ADDR))
#define LDSM4T(R0, R1, R2, R3, ADDR) \
    asm volatile("ldmatrix.sync.aligned.m8n8.x4.trans.shared.b16 {%0,%1,%2,%3}, [%4];" \
        : "=r"(R0), "=r"(R1), "=r"(R2), "=r"(R3) : "r"(ADDR))
#define CPA16(dst, src) \
    asm volatile("cp.async.ca.shared.global [%0], [%1], 16;" \
        :: "r"(dst), "l"(src) : "memory")
#define CPA_COMMIT() asm volatile("cp.async.commit_group;" ::: "memory")
#define CPA_WAIT1()  asm volatile("cp.async.wait_group 1;" ::: "memory")
#define CPA_WAIT2()  asm volatile("cp.async.wait_group 2;" ::: "memory")
#define CPA_WAIT3()  asm volatile("cp.async.wait_group 3;" ::: "memory")

// ---------------- merged weight prep ----------------------------------------
__device__ __forceinline__ void transpose_tile(
    const float* __restrict__ W, __half* __restrict__ WT, int K, int N,
    int bx, int by, int scale_rows, float scale)
{
    __shared__ float t[32][33];
    int tx = threadIdx.x & 31, ty = threadIdx.x >> 5;
    #pragma unroll
    for (int i = 0; i < 4; i++)
        t[ty + i * 8][tx] = W[(size_t)(by * 32 + ty + i * 8) * N + bx * 32 + tx];
    __syncthreads();
    #pragma unroll
    for (int i = 0; i < 4; i++) {
        int n = bx * 32 + ty + i * 8;
        float v = t[tx][ty + i * 8];
        if (n < scale_rows) v *= scale;
        WT[(size_t)n * K + by * 32 + tx] = __float2half_rn(v);
    }
}

__global__ __launch_bounds__(256) void prep_weights(
    const float* __restrict__ Wqkv, const float* __restrict__ Wo,
    const float* __restrict__ W1,   const float* __restrict__ W2,
    __half* __restrict__ wt)
{
    int l = blockIdx.z;
    __half* wl = wt + (size_t)l * WT_LAYER;
    int bid = blockIdx.x;
    if (bid < 3072) {
        transpose_tile(Wqkv + (size_t)l * 1024 * 3072, wl + WT_QKV,
                       1024, 3072, bid % 96, bid / 96, 1024, SCALE_QLOG2);
    } else if (bid < 4096) {
        bid -= 3072;
        transpose_tile(Wo + (size_t)l * 1024 * 1024, wl + WT_O,
                       1024, 1024, bid % 32, bid / 32, 0, 1.f);
    } else if (bid < 6144) {
        bid -= 4096;
        transpose_tile(W1 + (size_t)l * 1024 * 2048, wl + WT_W1,
                       1024, 2048, bid % 64, bid / 64, 0, 1.f);
    } else {
        bid -= 6144;
        transpose_tile(W2 + (size_t)l * 2048 * 1024, wl + WT_W2,
                       2048, 1024, bid % 32, bid / 32, 0, 1.f);
    }
}

// ---------------- embedding + PE + qkv bias scaling -------------------------
__global__ __launch_bounds__(256) void embed_bias_kernel(
    const int* __restrict__ tokens, const float* __restrict__ emb,
    float* __restrict__ x, __half* __restrict__ xh,
    const float* __restrict__ bqkv, float* __restrict__ bqs)
{
    if (blockIdx.x >= NROWS) {
        int i = (blockIdx.x - NROWS) * 256 + threadIdx.x;
        float v = bqkv[i];
        bqs[i] = ((i % 3072) < 1024) ? v * SCALE_QLOG2 : v;
        return;
    }
    int row = blockIdx.x;
    int tok = tokens[row];
    float tpos = (float)(row & (TSEQ - 1));
    int c = threadIdx.x * 4;
    float4 e = *(const float4*)(emb + (size_t)tok * DM + c);
    float o[4] = {e.x, e.y, e.z, e.w};
    #pragma unroll
    for (int q = 0; q < 4; q++) {
        int cc = c + q;
        float fi = (float)(cc & ~1);
        float ang = tpos * __expf(fi * -0.00899447301950799f);
        o[q] += (cc & 1) ? cosf(ang) : sinf(ang);
    }
    float4 r; r.x = o[0]; r.y = o[1]; r.z = o[2]; r.w = o[3];
    *(float4*)(x + (size_t)row * DM + c) = r;
    uint2 u; u.x = pack_half2(o[0], o[1]); u.y = pack_half2(o[2], o[3]);
    *(uint2*)(xh + (size_t)row * DM + c) = u;
}

// ---------------- fp16 HMMA GEMM: 128x128 tile, 3-ring, 2 CTAs/SM -----------
// C[M,N] = A[M,K] @ B[N,K]^T + bias. mode: bit0=relu, bit1=half-out
#define GAST 72
#define STG_H (256 * GAST)                 // A 128 rows + B 128 rows (halves)
#define GEMM_SMEM (3 * STG_H * 2)          // 110,592 B

__global__ __launch_bounds__(256, 2) void gemm_f16(
    const __half* __restrict__ A, const __half* __restrict__ B,
    const float* __restrict__ bias, void* __restrict__ Cout,
    int M, int N, int K, int mode)
{
    extern __shared__ __half sh[];
    uint32_t sbase = smem_u32(sh);
    int tid = threadIdx.x, w = tid >> 5, lane = tid & 31;
    int g = lane >> 2, t = lane & 3;
    int wm = w >> 2, wn = w & 3;                 // warp tile 64x32
    int rowBase = blockIdx.y * 128, colBase = blockIdx.x * 128;

    float acc[4][4][4];
    #pragma unroll
    for (int i = 0; i < 4; i++)
        #pragma unroll
        for (int j = 0; j < 4; j++)
            #pragma unroll
            for (int r = 0; r < 4; r++) acc[i][j][r] = 0.f;

    const int nc = K >> 6;

    // prologue: chunks 0,1
    #pragma unroll
    for (int c0 = 0; c0 < 2; ++c0) {
        uint32_t st = sbase + (uint32_t)c0 * (STG_H * 2);
        int kb = c0 * 64;
        #pragma unroll
        for (int it = 0; it < 4; ++it) {
            int p = tid + it * 256;
            int r = p >> 3, c8 = (p & 7) * 8;
            CPA16(st + (uint32_t)(r * GAST + c8) * 2u,
                  A + (size_t)(rowBase + r) * K + kb + c8);
            CPA16(st + (uint32_t)((128 + r) * GAST + c8) * 2u,
                  B + (size_t)(colBase + r) * K + kb + c8);
        }
        CPA_COMMIT();
    }

    int lm = lane & 15, lh8 = ((lane >> 4) & 1) * 8;
    int bn = (lane & 7) + (((lane >> 4) & 1) * 8);
    int bk8 = ((lane >> 3) & 1) * 8;

    for (int c = 0; c < nc; ++c) {
        CPA_WAIT1();
        __syncthreads();

        // prefetch chunk c+2 into ring (c+2)%3 (buffer consumed at c-1)
        int cn = c + 2;
        if (cn < nc) {
            uint32_t s2 = sbase + (uint32_t)(cn % 3) * (STG_H * 2);
            int kb = cn * 64;
            #pragma unroll
            for (int it = 0; it < 4; ++it) {
                int p = tid + it * 256;
                int r = p >> 3, c8 = (p & 7) * 8;
                CPA16(s2 + (uint32_t)(r * GAST + c8) * 2u,
                      A + (size_t)(rowBase + r) * K + kb + c8);
                CPA16(s2 + (uint32_t)((128 + r) * GAST + c8) * 2u,
                      B + (size_t)(colBase + r) * K + kb + c8);
            }
        }
        CPA_COMMIT();

        uint32_t st = sbase + (uint32_t)(c % 3) * (STG_H * 2);
        uint32_t aB = st, bB = st + 128 * GAST * 2;

        #pragma unroll
        for (int ks = 0; ks < 4; ++ks) {
            uint32_t af[4][4], bf[4][2];
            #pragma unroll
            for (int mt = 0; mt < 4; ++mt) {
                int m0 = wm * 64 + mt * 16;
                uint32_t ad = aB + (uint32_t)((m0 + lm) * GAST + ks * 16 + lh8) * 2u;
                LDSM4(af[mt][0], af[mt][1], af[mt][2], af[mt][3], ad);
            }
            #pragma unroll
            for (int j = 0; j < 2; ++j) {
                int n0 = wn * 32 + j * 16;
                uint32_t bd = bB + (uint32_t)((n0 + bn) * GAST + ks * 16 + bk8) * 2u;
                LDSM4(bf[2*j][0], bf[2*j][1], bf[2*j+1][0], bf[2*j+1][1], bd);
            }
            #pragma unroll
            for (int mt = 0; mt < 4; ++mt)
                #pragma unroll
                for (int nt = 0; nt < 4; ++nt)
                    mma_f16(acc[mt][nt][0], acc[mt][nt][1],
                            acc[mt][nt][2], acc[mt][nt][3],
                            af[mt][0], af[mt][1], af[mt][2], af[mt][3],
                            bf[nt][0], bf[nt][1]);
        }
    }

    int relu = mode & 1, hout = mode & 2;
    #pragma unroll
    for (int mt = 0; mt < 4; ++mt) {
        int r0g = rowBase + wm * 64 + mt * 16 + g;
        #pragma unroll
        for (int nt = 0; nt < 4; ++nt) {
            int cc = colBase + wn * 32 + nt * 8 + 2 * t;
            float b0 = bias[cc], b1 = bias[cc + 1];
            float v0 = acc[mt][nt][0] + b0, v1 = acc[mt][nt][1] + b1;
            float v2 = acc[mt][nt][2] + b0, v3 = acc[mt][nt][3] + b1;
            if (relu) {
                v0 = fmaxf(v0, 0.f); v1 = fmaxf(v1, 0.f);
                v2 = fmaxf(v2, 0.f); v3 = fmaxf(v3, 0.f);
            }
            if (hout) {
                *(uint32_t*)((__half*)Cout + (size_t)r0g * N + cc) = pack_half2(v0, v1);
                *(uint32_t*)((__half*)Cout + (size_t)(r0g + 8) * N + cc) = pack_half2(v2, v3);
            } else {
                float2 p0; p0.x = v0; p0.y = v1;
                float2 p1; p1.x = v2; p1.y = v3;
                *(float2*)((float*)Cout + (size_t)r0g * N + cc) = p0;
                *(float2*)((float*)Cout + (size_t)(r0g + 8) * N + cc) = p1;
            }
        }
    }
}

// ---------------- fp16 flash attention (unchanged from R8) ------------------
#define FQST 72
#define FKST 72
#define FQ_OFF 0
#define FKBUF  (64 * FKST)
#define FK_OFF (128 * FQST)
#define FV_OFF (FK_OFF + 4 * FKBUF)
#define ATT_SMEM ((FV_OFF + 4 * FKBUF) * 2)
#define NTILE (TSEQ / 64)

__global__ __launch_bounds__(256, 2) void flash_f16(
    const __half* __restrict__ qkv, __half* __restrict__ attn)
{
    extern __shared__ __half sf[];
    uint32_t sbase = smem_u32(sf);
    int tid = threadIdx.x, w = tid >> 5, lane = tid & 31;
    int g = lane >> 2, t = lane & 3;
    int h = blockIdx.y, b = blockIdx.z;
    int btQ = b * TSEQ + blockIdx.x * 128;
    int rl0 = w * 16;
    int lm = lane & 15, lh8 = ((lane >> 4) & 1) * 8;
    int bn = (lane & 7) + (((lane >> 4) & 1) * 8);
    int bk8 = ((lane >> 3) & 1) * 8;

    #pragma unroll
    for (int it = 0; it < 4; ++it) {
        int p = tid + it * 256;
        int r = p >> 3, c8 = (p & 7) * 8;
        CPA16(sbase + (uint32_t)(FQ_OFF + r * FQST + c8) * 2u,
              qkv + (size_t)(btQ + r) * 3072 + h * 64 + c8);
    }
    CPA_COMMIT();

    #pragma unroll
    for (int i0 = 0; i0 < 3; ++i0) {
        #pragma unroll
        for (int it = 0; it < 2; ++it) {
            int p = tid + it * 256;
            int r = p >> 3, c8 = (p & 7) * 8;
            const __half* src = qkv + (size_t)(b * TSEQ + i0 * 64 + r) * 3072 + h * 64;
            CPA16(sbase + (uint32_t)(FK_OFF + i0 * FKBUF + r * FKST + c8) * 2u,
                  src + 1024 + c8);
            CPA16(sbase + (uint32_t)(FV_OFF + i0 * FKBUF + r * FKST + c8) * 2u,
                  src + 2048 + c8);
        }
        CPA_COMMIT();
    }

    CPA_WAIT3();
    __syncthreads();

    float o[8][4];
    #pragma unroll
    for (int d = 0; d < 8; d++)
        #pragma unroll
        for (int r = 0; r < 4; r++) o[d][r] = 0.f;
    float m0 = -1e30f, m1 = -1e30f, l0 = 0.f, l1 = 0.f;

    for (int c = 0; c < NTILE; ++c) {
        CPA_WAIT2();
        __syncthreads();

        int cn = c + 3;
        if (cn < NTILE) {
            int rb = cn & 3;
            #pragma unroll
            for (int it = 0; it < 2; ++it) {
                int p = tid + it * 256;
                int r = p >> 3, c8 = (p & 7) * 8;
                const __half* src = qkv + (size_t)(b * TSEQ + cn * 64 + r) * 3072 + h * 64;
                CPA16(sbase + (uint32_t)(FK_OFF + rb * FKBUF + r * FKST + c8) * 2u,
                      src + 1024 + c8);
                CPA16(sbase + (uint32_t)(FV_OFF + rb * FKBUF + r * FKST + c8) * 2u,
                      src + 2048 + c8);
            }
        }
        CPA_COMMIT();

        uint32_t kB = sbase + (uint32_t)(FK_OFF + (c & 3) * FKBUF) * 2u;
        uint32_t vB = sbase + (uint32_t)(FV_OFF + (c & 3) * FKBUF) * 2u;

        float s[8][4];
        #pragma unroll
        for (int nt = 0; nt < 8; ++nt)
            s[nt][0] = s[nt][1] = s[nt][2] = s[nt][3] = 0.f;
        #pragma unroll
        for (int ks = 0; ks < 4; ++ks) {
            uint32_t qa[4];
            uint32_t qd = sbase + (uint32_t)(FQ_OFF + (rl0 + lm) * FQST + ks * 16 + lh8) * 2u;
            LDSM4(qa[0], qa[1], qa[2], qa[3], qd);
            uint32_t kf[8][2];
            #pragma unroll
            for (int j = 0; j < 4; ++j) {
                uint32_t kd = kB + (uint32_t)((j * 16 + bn) * FKST + ks * 16 + bk8) * 2u;
                LDSM4(kf[2*j][0], kf[2*j][1], kf[2*j+1][0], kf[2*j+1][1], kd);
            }
            #pragma unroll
            for (int nt = 0; nt < 8; ++nt)
                mma_f16(s[nt][0], s[nt][1], s[nt][2], s[nt][3],
                        qa[0], qa[1], qa[2], qa[3], kf[nt][0], kf[nt][1]);
        }

        float mx0 = -1e30f, mx1 = -1e30f;
        #pragma unroll
        for (int nt = 0; nt < 8; ++nt) {
            mx0 = fmaxf(mx0, fmaxf(s[nt][0], s[nt][1]));
            mx1 = fmaxf(mx1, fmaxf(s[nt][2], s[nt][3]));
        }
        mx0 = fmaxf(mx0, __shfl_xor_sync(0xffffffffu, mx0, 1));
        mx0 = fmaxf(mx0, __shfl_xor_sync(0xffffffffu, mx0, 2));
        mx1 = fmaxf(mx1, __shfl_xor_sync(0xffffffffu, mx1, 1));
        mx1 = fmaxf(mx1, __shfl_xor_sync(0xffffffffu, mx1, 2));
        float nm0 = fmaxf(m0, mx0), nm1 = fmaxf(m1, mx1);
        float al0 = ex2(m0 - nm0), al1 = ex2(m1 - nm1);
        m0 = nm0; m1 = nm1;

        float rs0 = 0.f, rs1 = 0.f;
        uint32_t pa[4][4];
        #pragma unroll
        for (int j = 0; j < 4; ++j) {
            float p00 = ex2(s[2*j][0] - m0),   p01 = ex2(s[2*j][1] - m0);
            float p02 = ex2(s[2*j][2] - m1),   p03 = ex2(s[2*j][3] - m1);
            float p10 = ex2(s[2*j+1][0] - m0), p11 = ex2(s[2*j+1][1] - m0);
            float p12 = ex2(s[2*j+1][2] - m1), p13 = ex2(s[2*j+1][3] - m1);
            rs0 += p00 + p01 + p10 + p11;
            rs1 += p02 + p03 + p12 + p13;
            pa[j][0] = pack_half2(p00, p01);
            pa[j][1] = pack_half2(p02, p03);
            pa[j][2] = pack_half2(p10, p11);
            pa[j][3] = pack_half2(p12, p13);
        }
        rs0 += __shfl_xor_sync(0xffffffffu, rs0, 1);
        rs0 += __shfl_xor_sync(0xffffffffu, rs0, 2);
        rs1 += __shfl_xor_sync(0xffffffffu, rs1, 1);
        rs1 += __shfl_xor_sync(0xffffffffu, rs1, 2);
        l0 = l0 * al0 + rs0;
        l1 = l1 * al1 + rs1;
        #pragma unroll
        for (int d = 0; d < 8; d++) {
            o[d][0] *= al0; o[d][1] *= al0;
            o[d][2] *= al1; o[d][3] *= al1;
        }

        #pragma unroll
        for (int ks = 0; ks < 4; ++ks) {
            uint32_t vf[8][2];
            #pragma unroll
            for (int j = 0; j < 4; ++j) {
                uint32_t vd = vB + (uint32_t)((ks * 16 + lm) * FKST + j * 16 + lh8) * 2u;
                LDSM4T(vf[2*j][0], vf[2*j][1], vf[2*j+1][0], vf[2*j+1][1], vd);
            }
            #pragma unroll
            for (int dt = 0; dt < 8; ++dt)
                mma_f16(o[dt][0], o[dt][1], o[dt][2], o[dt][3],
                        pa[ks][0], pa[ks][1], pa[ks][2], pa[ks][3],
                        vf[dt][0], vf[dt][1]);
        }
    }

    float i0 = 1.f / l0, i1 = 1.f / l1;
    #pragma unroll
    for (int dt = 0; dt < 8; ++dt) {
        size_t base = (size_t)(btQ + rl0 + g) * DM + h * 64 + dt * 8 + 2 * t;
        *(uint32_t*)(attn + base) = pack_half2(o[dt][0] * i0, o[dt][1] * i0);
        *(uint32_t*)(attn + base + 8 * DM) = pack_half2(o[dt][2] * i1, o[dt][3] * i1);
    }
}

// ---------------- fused residual add + LayerNorm ----------------------------
__global__ __launch_bounds__(256) void add_ln_kernel(
    const float* __restrict__ x, const float* __restrict__ y,
    const float* __restrict__ g, const float* __restrict__ b,
    float* __restrict__ outp, __half* __restrict__ oh)
{
    __shared__ float red[8];
    __shared__ float bc;
    int row = blockIdx.x, tid = threadIdx.x;
    int lane = tid & 31, warp = tid >> 5;

    float4 xv = *(const float4*)(x + (size_t)row * DM + tid * 4);
    float4 yv = *(const float4*)(y + (size_t)row * DM + tid * 4);
    float v0 = xv.x + yv.x, v1 = xv.y + yv.y, v2 = xv.z + yv.z, v3 = xv.w + yv.w;

    float s = v0 + v1 + v2 + v3;
    #pragma unroll
    for (int off = 16; off > 0; off >>= 1) s += __shfl_xor_sync(0xffffffffu, s, off);
    if (lane == 0) red[warp] = s;
    __syncthreads();
    if (tid < 8) {
        float tt = red[tid];
        #pragma unroll
        for (int off = 4; off > 0; off >>= 1) tt += __shfl_xor_sync(0xffu, tt, off);
        if (tid == 0) bc = tt;
    }
    __syncthreads();
    float mean = bc * (1.f / (float)DM);

    float d0 = v0 - mean, d1 = v1 - mean, d2 = v2 - mean, d3 = v3 - mean;
    float sq = d0 * d0 + d1 * d1 + d2 * d2 + d3 * d3;
    #pragma unroll
    for (int off = 16; off > 0; off >>= 1) sq += __shfl_xor_sync(0xffffffffu, sq, off);
    __syncthreads();
    if (lane == 0) red[warp] = sq;
    __syncthreads();
    if (tid < 8) {
        float tt = red[tid];
        #pragma unroll
        for (int off = 4; off > 0; off >>= 1) tt += __shfl_xor_sync(0xffu, tt, off);
        if (tid == 0) bc = tt;
    }
    __syncthreads();
    float rstd = rsqrtf(bc * (1.f / (float)DM) + 1e-5f);

    float4 gv = *(const float4*)(g + tid * 4);
    float4 bv = *(const float4*)(b + tid * 4);
    float4 ov;
    ov.x = d0 * rstd * gv.x + bv.x;
    ov.y = d1 * rstd * gv.y + bv.y;
    ov.z = d2 * rstd * gv.z + bv.z;
    ov.w = d3 * rstd * gv.w + bv.w;
    *(float4*)(outp + (size_t)row * DM + tid * 4) = ov;
    uint2 u; u.x = pack_half2(ov.x, ov.y); u.y = pack_half2(ov.z, ov.w);
    *(uint2*)(oh + (size_t)row * DM + tid * 4) = u;
}

// ---------------- launcher ---------------------------------------------------
extern "C" void kernel_launch(void* const* d_in, const int* in_sizes, int n_in,
                              void* d_out, int out_size)
{
    (void)in_sizes; (void)n_in; (void)out_size;
    const int*   tokens = (const int*)  d_in[0];
    const float* emb  = (const float*)d_in[1];
    const float* Wqkv = (const float*)d_in[2];
    const float* bqkv = (const float*)d_in[3];
    const float* Wo   = (const float*)d_in[4];
    const float* bo   = (const float*)d_in[5];
    const float* g1   = (const float*)d_in[6];
    const float* be1  = (const float*)d_in[7];
    const float* W1   = (const float*)d_in[8];
    const float* bf1  = (const float*)d_in[9];
    const float* W2   = (const float*)d_in[10];
    const float* bf2  = (const float*)d_in[11];
    const float* g2   = (const float*)d_in[12];
    const float* be2  = (const float*)d_in[13];
    float* outp = (float*)d_out;

    float *x, *proj, *ff2, *bqs;
    __half *xh, *qkv, *attn, *ff1, *wt;
    cudaGetSymbolAddress((void**)&x,    g_x);
    cudaGetSymbolAddress((void**)&xh,   g_xh);
    cudaGetSymbolAddress((void**)&qkv,  g_qkv);
    cudaGetSymbolAddress((void**)&attn, g_attn);
    cudaGetSymbolAddress((void**)&proj, g_proj);
    cudaGetSymbolAddress((void**)&ff1,  g_ff1);
    cudaGetSymbolAddress((void**)&ff2,  g_ff2);
    cudaGetSymbolAddress((void**)&wt,   g_wt);
    cudaGetSymbolAddress((void**)&bqs,  g_bqs);

    cudaFuncSetAttribute(gemm_f16, cudaFuncAttributeMaxDynamicSharedMemorySize,
                         GEMM_SMEM);
    cudaFuncSetAttribute(flash_f16, cudaFuncAttributeMaxDynamicSharedMemorySize,
                         ATT_SMEM);

    prep_weights<<<dim3(8192, 1, 6), 256>>>(Wqkv, Wo, W1, W2, wt);          // 0
    embed_bias_kernel<<<NROWS + 72, 256>>>(tokens, emb, x, xh, bqkv, bqs);  // 1

    for (int l = 0; l < 6; ++l) {
        __half* wl = wt + (size_t)l * WT_LAYER;

        gemm_f16<<<dim3(3072 / 128, NROWS / 128), 256, GEMM_SMEM>>>(
            xh, wl + WT_QKV, bqs + (size_t)l * 3072, qkv,
            NROWS, 3 * DM, DM, 2);

        flash_f16<<<dim3(TSEQ / 128, 16, 4), 256, ATT_SMEM>>>(qkv, attn);

        gemm_f16<<<dim3(1024 / 128, NROWS / 128), 256, GEMM_SMEM>>>(
            attn, wl + WT_O, bo + (size_t)l * DM, proj,
            NROWS, DM, DM, 0);

        add_ln_kernel<<<NROWS, 256>>>(x, proj, g1 + (size_t)l * DM,
                                      be1 + (size_t)l * DM, x, xh);

        gemm_f16<<<dim3(2048 / 128, NROWS / 128), 256, GEMM_SMEM>>>(
            xh, wl + WT_W1, bf1 + (size_t)l * DFF, ff1,
            NROWS, DFF, DM, 3);

        gemm_f16<<<dim3(1024 / 128, NROWS / 128), 256, GEMM_SMEM>>>(
            ff1, wl + WT_W2, bf2 + (size_t)l * DM, ff2,
            NROWS, DM, DFF, 0);

        add_ln_kernel<<<NROWS, 256>>>(x, ff2, g2 + (size_t)l * DM,
                                      be2 + (size_t)l * DM,
                                      (l == 5) ? outp : x, xh);
    }
}

// round 12
// speedup vs baseline: 1.0843x; 1.0078x over previous
#include <cuda_runtime.h>
#include <cuda_fp16.h>
#include <math.h>
#include <stdint.h>

// Problem constants
#define NROWS 8192      // B*T
#define TSEQ  2048
#define DM    1024
#define DFF   2048

#define SCALE_QLOG2 0.18033688011112042f   // (1/sqrt(64)) * log2(e)

// ---------------- scratch (static device globals) ---------------------------
__device__ float  g_x   [NROWS * DM];
__device__ __half g_xh  [NROWS * DM];
__device__ __half g_qkv [NROWS * 3 * DM];
__device__ __half g_attn[NROWS * DM];
__device__ float  g_proj[NROWS * DM];
__device__ __half g_ff1 [NROWS * DFF];
__device__ float  g_ff2 [NROWS * DM];

#define WT_QKV 0
#define WT_O   (3072 * 1024)
#define WT_W1  (WT_O + 1024 * 1024)
#define WT_W2  (WT_W1 + 2048 * 1024)
#define WT_LAYER (WT_W2 + 1024 * 2048)
__device__ __half g_wt[6 * WT_LAYER];
__device__ float  g_bqs[6 * 3072];

// ---------------- PTX helpers ------------------------------------------------
__device__ __forceinline__ float ex2(float x) {
    float y; asm("ex2.approx.f32 %0, %1;" : "=f"(y) : "f"(x)); return y;
}
__device__ __forceinline__ uint32_t pack_half2(float lo, float hi) {
    uint32_t u;
    asm("cvt.rn.f16x2.f32 %0, %1, %2;" : "=r"(u) : "f"(hi), "f"(lo));
    return u;
}
__device__ __forceinline__ void mma_f16(
    float& d0, float& d1, float& d2, float& d3,
    uint32_t a0, uint32_t a1, uint32_t a2, uint32_t a3,
    uint32_t b0, uint32_t b1)
{
    asm volatile(
        "mma.sync.aligned.m16n8k16.row.col.f32.f16.f16.f32 "
        "{%0,%1,%2,%3},{%4,%5,%6,%7},{%8,%9},{%0,%1,%2,%3};\n"
        : "+f"(d0), "+f"(d1), "+f"(d2), "+f"(d3)
        : "r"(a0), "r"(a1), "r"(a2), "r"(a3), "r"(b0), "r"(b1));
}
__device__ __forceinline__ uint32_t smem_u32(const void* p) {
    uint32_t a;
    asm("{ .reg .u64 t; cvta.to.shared.u64 t, %1; cvt.u32.u64 %0, t; }"
        : "=r"(a) : "l"(p));
    return a;
}
#define LDSM4(R0, R1, R2, R3, ADDR) \
    asm volatile("ldmatrix.sync.aligned.m8n8.x4.shared.b16 {%0,%1,%2,%3}, [%4];" \
        : "=r"(R0), "=r"(R1), "=r"(R2), "=r"(R3) : "r"(ADDR))
#define LDSM4T(R0, R1, R2, R3, ADDR) \
    asm volatile("ldmatrix.sync.aligned.m8n8.x4.trans.shared.b16 {%0,%1,%2,%3}, [%4];" \
        : "=r"(R0), "=r"(R1), "=r"(R2), "=r"(R3) : "r"(ADDR))
#define CPA16(dst, src) \
    asm volatile("cp.async.ca.shared.global [%0], [%1], 16;" \
        :: "r"(dst), "l"(src) : "memory")
#define CPA_COMMIT() asm volatile("cp.async.commit_group;" ::: "memory")
#define CPA_WAIT1()  asm volatile("cp.async.wait_group 1;" ::: "memory")
#define CPA_WAIT2()  asm volatile("cp.async.wait_group 2;" ::: "memory")
#define CPA_WAIT3()  asm volatile("cp.async.wait_group 3;" ::: "memory")

// ---------------- weight prep ------------------------------------------------
__device__ __forceinline__ void transpose_tile(
    const float* __restrict__ W, __half* __restrict__ WT, int K, int N,
    int bx, int by, int scale_rows, float scale)
{
    __shared__ float t[32][33];
    int tx = threadIdx.x & 31, ty = threadIdx.x >> 5;
    #pragma unroll
    for (int i = 0; i < 4; i++)
        t[ty + i * 8][tx] = W[(size_t)(by * 32 + ty + i * 8) * N + bx * 32 + tx];
    __syncthreads();
    #pragma unroll
    for (int i = 0; i < 4; i++) {
        int n = bx * 32 + ty + i * 8;
        float v = t[tx][ty + i * 8];
        if (n < scale_rows) v *= scale;
        WT[(size_t)n * K + by * 32 + tx] = __float2half_rn(v);
    }
}

__global__ __launch_bounds__(256) void prep_weights_a(
    const float* __restrict__ Wqkv, const float* __restrict__ Wo,
    __half* __restrict__ wt)
{
    int l = blockIdx.z;
    __half* wl = wt + (size_t)l * WT_LAYER;
    int bid = blockIdx.x;                       // 4096 = 3072 QKV + 1024 O
    if (bid < 3072) {
        transpose_tile(Wqkv + (size_t)l * 1024 * 3072, wl + WT_QKV,
                       1024, 3072, bid % 96, bid / 96, 1024, SCALE_QLOG2);
    } else {
        bid -= 3072;
        transpose_tile(Wo + (size_t)l * 1024 * 1024, wl + WT_O,
                       1024, 1024, bid % 32, bid / 32, 0, 1.f);
    }
}

__global__ __launch_bounds__(256) void prep_weights_b(
    const float* __restrict__ W1, const float* __restrict__ W2,
    __half* __restrict__ wt)
{
    int l = blockIdx.z;
    __half* wl = wt + (size_t)l * WT_LAYER;
    int bid = blockIdx.x;                       // 4096 = 2048 W1 + 2048 W2
    if (bid < 2048) {
        // W1: [K=1024, N=2048] -> 64 x 32 tiles
        transpose_tile(W1 + (size_t)l * 1024 * 2048, wl + WT_W1,
                       1024, 2048, bid % 64, bid / 64, 0, 1.f);
    } else {
        // W2: [K=2048, N=1024] -> 32 x 64 tiles = 2048 blocks (was 1024: BUG)
        bid -= 2048;
        transpose_tile(W2 + (size_t)l * 2048 * 1024, wl + WT_W2,
                       2048, 1024, bid % 32, bid / 32, 0, 1.f);
    }
}

// ---------------- embedding + PE + qkv bias scaling -------------------------
__global__ __launch_bounds__(256) void embed_bias_kernel(
    const int* __restrict__ tokens, const float* __restrict__ emb,
    float* __restrict__ x, __half* __restrict__ xh,
    const float* __restrict__ bqkv, float* __restrict__ bqs)
{
    if (blockIdx.x >= NROWS) {
        int i = (blockIdx.x - NROWS) * 256 + threadIdx.x;
        float v = bqkv[i];
        bqs[i] = ((i % 3072) < 1024) ? v * SCALE_QLOG2 : v;
        return;
    }
    int row = blockIdx.x;
    int tok = tokens[row];
    float tpos = (float)(row & (TSEQ - 1));
    int c = threadIdx.x * 4;
    float4 e = *(const float4*)(emb + (size_t)tok * DM + c);
    float o[4] = {e.x, e.y, e.z, e.w};
    #pragma unroll
    for (int q = 0; q < 4; q++) {
        int cc = c + q;
        float fi = (float)(cc & ~1);
        float ang = tpos * __expf(fi * -0.00899447301950799f);
        o[q] += (cc & 1) ? cosf(ang) : sinf(ang);
    }
    float4 r; r.x = o[0]; r.y = o[1]; r.z = o[2]; r.w = o[3];
    *(float4*)(x + (size_t)row * DM + c) = r;
    uint2 u; u.x = pack_half2(o[0], o[1]); u.y = pack_half2(o[2], o[3]);
    *(uint2*)(xh + (size_t)row * DM + c) = u;
}

// ---------------- fp16 HMMA GEMM: 128x128 tile, 3-ring, 2 CTAs/SM -----------
#define GAST 72
#define STG_H (256 * GAST)
#define GEMM_SMEM (3 * STG_H * 2)

__global__ __launch_bounds__(256, 2) void gemm_f16(
    const __half* __restrict__ A, const __half* __restrict__ B,
    const float* __restrict__ bias, void* __restrict__ Cout,
    int M, int N, int K, int mode)
{
    extern __shared__ __half sh[];
    uint32_t sbase = smem_u32(sh);
    int tid = threadIdx.x, w = tid >> 5, lane = tid & 31;
    int g = lane >> 2, t = lane & 3;
    int wm = w >> 2, wn = w & 3;
    int rowBase = blockIdx.y * 128, colBase = blockIdx.x * 128;

    float acc[4][4][4];
    #pragma unroll
    for (int i = 0; i < 4; i++)
        #pragma unroll
        for (int j = 0; j < 4; j++)
            #pragma unroll
            for (int r = 0; r < 4; r++) acc[i][j][r] = 0.f;

    const int nc = K >> 6;

    #pragma unroll
    for (int c0 = 0; c0 < 2; ++c0) {
        uint32_t st = sbase + (uint32_t)c0 * (STG_H * 2);
        int kb = c0 * 64;
        #pragma unroll
        for (int it = 0; it < 4; ++it) {
            int p = tid + it * 256;
            int r = p >> 3, c8 = (p & 7) * 8;
            CPA16(st + (uint32_t)(r * GAST + c8) * 2u,
                  A + (size_t)(rowBase + r) * K + kb + c8);
            CPA16(st + (uint32_t)((128 + r) * GAST + c8) * 2u,
                  B + (size_t)(colBase + r) * K + kb + c8);
        }
        CPA_COMMIT();
    }

    int lm = lane & 15, lh8 = ((lane >> 4) & 1) * 8;
    int bn = (lane & 7) + (((lane >> 4) & 1) * 8);
    int bk8 = ((lane >> 3) & 1) * 8;

    for (int c = 0; c < nc; ++c) {
        CPA_WAIT1();
        __syncthreads();

        int cn = c + 2;
        if (cn < nc) {
            uint32_t s2 = sbase + (uint32_t)(cn % 3) * (STG_H * 2);
            int kb = cn * 64;
            #pragma unroll
            for (int it = 0; it < 4; ++it) {
                int p = tid + it * 256;
                int r = p >> 3, c8 = (p & 7) * 8;
                CPA16(s2 + (uint32_t)(r * GAST + c8) * 2u,
                      A + (size_t)(rowBase + r) * K + kb + c8);
                CPA16(s2 + (uint32_t)((128 + r) * GAST + c8) * 2u,
                      B + (size_t)(colBase + r) * K + kb + c8);
            }
        }
        CPA_COMMIT();

        uint32_t st = sbase + (uint32_t)(c % 3) * (STG_H * 2);
        uint32_t aB = st, bB = st + 128 * GAST * 2;

        #pragma unroll
        for (int ks = 0; ks < 4; ++ks) {
            uint32_t af[4][4], bf[4][2];
            #pragma unroll
            for (int mt = 0; mt < 4; ++mt) {
                int m0 = wm * 64 + mt * 16;
                uint32_t ad = aB + (uint32_t)((m0 + lm) * GAST + ks * 16 + lh8) * 2u;
                LDSM4(af[mt][0], af[mt][1], af[mt][2], af[mt][3], ad);
            }
            #pragma unroll
            for (int j = 0; j < 2; ++j) {
                int n0 = wn * 32 + j * 16;
                uint32_t bd = bB + (uint32_t)((n0 + bn) * GAST + ks * 16 + bk8) * 2u;
                LDSM4(bf[2*j][0], bf[2*j][1], bf[2*j+1][0], bf[2*j+1][1], bd);
            }
            #pragma unroll
            for (int mt = 0; mt < 4; ++mt)
                #pragma unroll
                for (int nt = 0; nt < 4; ++nt)
                    mma_f16(acc[mt][nt][0], acc[mt][nt][1],
                            acc[mt][nt][2], acc[mt][nt][3],
                            af[mt][0], af[mt][1], af[mt][2], af[mt][3],
                            bf[nt][0], bf[nt][1]);
        }
    }

    int relu = mode & 1, hout = mode & 2;
    #pragma unroll
    for (int mt = 0; mt < 4; ++mt) {
        int r0g = rowBase + wm * 64 + mt * 16 + g;
        #pragma unroll
        for (int nt = 0; nt < 4; ++nt) {
            int cc = colBase + wn * 32 + nt * 8 + 2 * t;
            float b0 = bias[cc], b1 = bias[cc + 1];
            float v0 = acc[mt][nt][0] + b0, v1 = acc[mt][nt][1] + b1;
            float v2 = acc[mt][nt][2] + b0, v3 = acc[mt][nt][3] + b1;
            if (relu) {
                v0 = fmaxf(v0, 0.f); v1 = fmaxf(v1, 0.f);
                v2 = fmaxf(v2, 0.f); v3 = fmaxf(v3, 0.f);
            }
            if (hout) {
                *(uint32_t*)((__half*)Cout + (size_t)r0g * N + cc) = pack_half2(v0, v1);
                *(uint32_t*)((__half*)Cout + (size_t)(r0g + 8) * N + cc) = pack_half2(v2, v3);
            } else {
                float2 p0; p0.x = v0; p0.y = v1;
                float2 p1; p1.x = v2; p1.y = v3;
                *(float2*)((float*)Cout + (size_t)r0g * N + cc) = p0;
                *(float2*)((float*)Cout + (size_t)(r0g + 8) * N + cc) = p1;
            }
        }
    }
}

// ---------------- fp16 flash attention: exact online softmax ----------------
// Running max REQUIRED (P stored fp16; must stay <= 1). l kept per-thread,
// reduced once at the end (exact: alpha row-uniform, reduction linear).
#define FQST 72
#define FKST 72
#define FQ_OFF 0
#define FKBUF  (64 * FKST)
#define FK_OFF (128 * FQST)
#define FV_OFF (FK_OFF + 4 * FKBUF)
#define ATT_SMEM ((FV_OFF + 4 * FKBUF) * 2)
#define NTILE (TSEQ / 64)

__global__ __launch_bounds__(256, 2) void flash_f16(
    const __half* __restrict__ qkv, __half* __restrict__ attn)
{
    extern __shared__ __half sf[];
    uint32_t sbase = smem_u32(sf);
    int tid = threadIdx.x, w = tid >> 5, lane = tid & 31;
    int g = lane >> 2, t = lane & 3;
    int h = blockIdx.y, b = blockIdx.z;
    int btQ = b * TSEQ + blockIdx.x * 128;
    int rl0 = w * 16;
    int lm = lane & 15, lh8 = ((lane >> 4) & 1) * 8;
    int bn = (lane & 7) + (((lane >> 4) & 1) * 8);
    int bk8 = ((lane >> 3) & 1) * 8;

    #pragma unroll
    for (int it = 0; it < 4; ++it) {
        int p = tid + it * 256;
        int r = p >> 3, c8 = (p & 7) * 8;
        CPA16(sbase + (uint32_t)(FQ_OFF + r * FQST + c8) * 2u,
              qkv + (size_t)(btQ + r) * 3072 + h * 64 + c8);
    }
    CPA_COMMIT();

    #pragma unroll
    for (int i0 = 0; i0 < 3; ++i0) {
        #pragma unroll
        for (int it = 0; it < 2; ++it) {
            int p = tid + it * 256;
            int r = p >> 3, c8 = (p & 7) * 8;
            const __half* src = qkv + (size_t)(b * TSEQ + i0 * 64 + r) * 3072 + h * 64;
            CPA16(sbase + (uint32_t)(FK_OFF + i0 * FKBUF + r * FKST + c8) * 2u,
                  src + 1024 + c8);
            CPA16(sbase + (uint32_t)(FV_OFF + i0 * FKBUF + r * FKST + c8) * 2u,
                  src + 2048 + c8);
        }
        CPA_COMMIT();
    }

    CPA_WAIT3();
    __syncthreads();

    float o[8][4];
    #pragma unroll
    for (int d = 0; d < 8; d++)
        #pragma unroll
        for (int r = 0; r < 4; r++) o[d][r] = 0.f;
    float m0 = -1e30f, m1 = -1e30f;
    float l0p = 0.f, l1p = 0.f;

    for (int c = 0; c < NTILE; ++c) {
        CPA_WAIT2();
        __syncthreads();

        int cn = c + 3;
        if (cn < NTILE) {
            int rb = cn & 3;
            #pragma unroll
            for (int it = 0; it < 2; ++it) {
                int p = tid + it * 256;
                int r = p >> 3, c8 = (p & 7) * 8;
                const __half* src = qkv + (size_t)(b * TSEQ + cn * 64 + r) * 3072 + h * 64;
                CPA16(sbase + (uint32_t)(FK_OFF + rb * FKBUF + r * FKST + c8) * 2u,
                      src + 1024 + c8);
                CPA16(sbase + (uint32_t)(FV_OFF + rb * FKBUF + r * FKST + c8) * 2u,
                      src + 2048 + c8);
            }
        }
        CPA_COMMIT();

        uint32_t kB = sbase + (uint32_t)(FK_OFF + (c & 3) * FKBUF) * 2u;
        uint32_t vB = sbase + (uint32_t)(FV_OFF + (c & 3) * FKBUF) * 2u;

        float s[8][4];
        #pragma unroll
        for (int nt = 0; nt < 8; ++nt)
            s[nt][0] = s[nt][1] = s[nt][2] = s[nt][3] = 0.f;
        #pragma unroll
        for (int ks = 0; ks < 4; ++ks) {
            uint32_t qa[4];
            uint32_t qd = sbase + (uint32_t)(FQ_OFF + (rl0 + lm) * FQST + ks * 16 + lh8) * 2u;
            LDSM4(qa[0], qa[1], qa[2], qa[3], qd);
            uint32_t kf[8][2];
            #pragma unroll
            for (int j = 0; j < 4; ++j) {
                uint32_t kd = kB + (uint32_t)((j * 16 + bn) * FKST + ks * 16 + bk8) * 2u;
                LDSM4(kf[2*j][0], kf[2*j][1], kf[2*j+1][0], kf[2*j+1][1], kd);
            }
            #pragma unroll
            for (int nt = 0; nt < 8; ++nt)
                mma_f16(s[nt][0], s[nt][1], s[nt][2], s[nt][3],
                        qa[0], qa[1], qa[2], qa[3], kf[nt][0], kf[nt][1]);
        }

        float mx0 = -1e30f, mx1 = -1e30f;
        #pragma unroll
        for (int nt = 0; nt < 8; ++nt) {
            mx0 = fmaxf(mx0, fmaxf(s[nt][0], s[nt][1]));
            mx1 = fmaxf(mx1, fmaxf(s[nt][2], s[nt][3]));
        }
        mx0 = fmaxf(mx0, __shfl_xor_sync(0xffffffffu, mx0, 1));
        mx0 = fmaxf(mx0, __shfl_xor_sync(0xffffffffu, mx0, 2));
        mx1 = fmaxf(mx1, __shfl_xor_sync(0xffffffffu, mx1, 1));
        mx1 = fmaxf(mx1, __shfl_xor_sync(0xffffffffu, mx1, 2));
        float nm0 = fmaxf(m0, mx0), nm1 = fmaxf(m1, mx1);
        float al0 = ex2(m0 - nm0), al1 = ex2(m1 - nm1);
        m0 = nm0; m1 = nm1;

        uint32_t pa[4][4];
        float rs0 = 0.f, rs1 = 0.f;
        #pragma unroll
        for (int j = 0; j < 4; ++j) {
            float p00 = ex2(s[2*j][0] - m0),   p01 = ex2(s[2*j][1] - m0);
            float p02 = ex2(s[2*j][2] - m1),   p03 = ex2(s[2*j][3] - m1);
            float p10 = ex2(s[2*j+1][0] - m0), p11 = ex2(s[2*j+1][1] - m0);
            float p12 = ex2(s[2*j+1][2] - m1), p13 = ex2(s[2*j+1][3] - m1);
            rs0 += p00 + p01 + p10 + p11;
            rs1 += p02 + p03 + p12 + p13;
            pa[j][0] = pack_half2(p00, p01);
            pa[j][1] = pack_half2(p02, p03);
            pa[j][2] = pack_half2(p10, p11);
            pa[j][3] = pack_half2(p12, p13);
        }
        l0p = l0p * al0 + rs0;
        l1p = l1p * al1 + rs1;
        #pragma unroll
        for (int d = 0; d < 8; d++) {
            o[d][0] *= al0; o[d][1] *= al0;
            o[d][2] *= al1; o[d][3] *= al1;
        }

        #pragma unroll
        for (int ks = 0; ks < 4; ++ks) {
            uint32_t vf[8][2];
            #pragma unroll
            for (int j = 0; j < 4; ++j) {
                uint32_t vd = vB + (uint32_t)((ks * 16 + lm) * FKST + j * 16 + lh8) * 2u;
                LDSM4T(vf[2*j][0], vf[2*j][1], vf[2*j+1][0], vf[2*j+1][1], vd);
            }
            #pragma unroll
            for (int dt = 0; dt < 8; ++dt)
                mma_f16(o[dt][0], o[dt][1], o[dt][2], o[dt][3],
                        pa[ks][0], pa[ks][1], pa[ks][2], pa[ks][3],
                        vf[dt][0], vf[dt][1]);
        }
    }

    l0p += __shfl_xor_sync(0xffffffffu, l0p, 1);
    l0p += __shfl_xor_sync(0xffffffffu, l0p, 2);
    l1p += __shfl_xor_sync(0xffffffffu, l1p, 1);
    l1p += __shfl_xor_sync(0xffffffffu, l1p, 2);

    float i0 = 1.f / l0p, i1 = 1.f / l1p;
    #pragma unroll
    for (int dt = 0; dt < 8; ++dt) {
        size_t base = (size_t)(btQ + rl0 + g) * DM + h * 64 + dt * 8 + 2 * t;
        *(uint32_t*)(attn + base) = pack_half2(o[dt][0] * i0, o[dt][1] * i0);
        *(uint32_t*)(attn + base + 8 * DM) = pack_half2(o[dt][2] * i1, o[dt][3] * i1);
    }
}

// ---------------- fused residual add + LayerNorm ----------------------------
__global__ __launch_bounds__(256) void add_ln_kernel(
    const float* __restrict__ x, const float* __restrict__ y,
    const float* __restrict__ g, const float* __restrict__ b,
    float* __restrict__ outp, __half* __restrict__ oh)
{
    __shared__ float red[8];
    __shared__ float bc;
    int row = blockIdx.x, tid = threadIdx.x;
    int lane = tid & 31, warp = tid >> 5;

    float4 xv = *(const float4*)(x + (size_t)row * DM + tid * 4);
    float4 yv = *(const float4*)(y + (size_t)row * DM + tid * 4);
    float v0 = xv.x + yv.x, v1 = xv.y + yv.y, v2 = xv.z + yv.z, v3 = xv.w + yv.w;

    float s = v0 + v1 + v2 + v3;
    #pragma unroll
    for (int off = 16; off > 0; off >>= 1) s += __shfl_xor_sync(0xffffffffu, s, off);
    if (lane == 0) red[warp] = s;
    __syncthreads();
    if (tid < 8) {
        float tt = red[tid];
        #pragma unroll
        for (int off = 4; off > 0; off >>= 1) tt += __shfl_xor_sync(0xffu, tt, off);
        if (tid == 0) bc = tt;
    }
    __syncthreads();
    float mean = bc * (1.f / (float)DM);

    float d0 = v0 - mean, d1 = v1 - mean, d2 = v2 - mean, d3 = v3 - mean;
    float sq = d0 * d0 + d1 * d1 + d2 * d2 + d3 * d3;
    #pragma unroll
    for (int off = 16; off > 0; off >>= 1) sq += __shfl_xor_sync(0xffffffffu, sq, off);
    __syncthreads();
    if (lane == 0) red[warp] = sq;
    __syncthreads();
    if (tid < 8) {
        float tt = red[tid];
        #pragma unroll
        for (int off = 4; off > 0; off >>= 1) tt += __shfl_xor_sync(0xffu, tt, off);
        if (tid == 0) bc = tt;
    }
    __syncthreads();
    float rstd = rsqrtf(bc * (1.f / (float)DM) + 1e-5f);

    float4 gv = *(const float4*)(g + tid * 4);
    float4 bv = *(const float4*)(b + tid * 4);
    float4 ov;
    ov.x = d0 * rstd * gv.x + bv.x;
    ov.y = d1 * rstd * gv.y + bv.y;
    ov.z = d2 * rstd * gv.z + bv.z;
    ov.w = d3 * rstd * gv.w + bv.w;
    *(float4*)(outp + (size_t)row * DM + tid * 4) = ov;
    uint2 u; u.x = pack_half2(ov.x, ov.y); u.y = pack_half2(ov.z, ov.w);
    *(uint2*)(oh + (size_t)row * DM + tid * 4) = u;
}

// ---------------- launcher ---------------------------------------------------
extern "C" void kernel_launch(void* const* d_in, const int* in_sizes, int n_in,
                              void* d_out, int out_size)
{
    (void)in_sizes; (void)n_in; (void)out_size;
    const int*   tokens = (const int*)  d_in[0];
    const float* emb  = (const float*)d_in[1];
    const float* Wqkv = (const float*)d_in[2];
    const float* bqkv = (const float*)d_in[3];
    const float* Wo   = (const float*)d_in[4];
    const float* bo   = (const float*)d_in[5];
    const float* g1   = (const float*)d_in[6];
    const float* be1  = (const float*)d_in[7];
    const float* W1   = (const float*)d_in[8];
    const float* bf1  = (const float*)d_in[9];
    const float* W2   = (const float*)d_in[10];
    const float* bf2  = (const float*)d_in[11];
    const float* g2   = (const float*)d_in[12];
    const float* be2  = (const float*)d_in[13];
    float* outp = (float*)d_out;

    float *x, *proj, *ff2, *bqs;
    __half *xh, *qkv, *attn, *ff1, *wt;
    cudaGetSymbolAddress((void**)&x,    g_x);
    cudaGetSymbolAddress((void**)&xh,   g_xh);
    cudaGetSymbolAddress((void**)&qkv,  g_qkv);
    cudaGetSymbolAddress((void**)&attn, g_attn);
    cudaGetSymbolAddress((void**)&proj, g_proj);
    cudaGetSymbolAddress((void**)&ff1,  g_ff1);
    cudaGetSymbolAddress((void**)&ff2,  g_ff2);
    cudaGetSymbolAddress((void**)&wt,   g_wt);
    cudaGetSymbolAddress((void**)&bqs,  g_bqs);

    cudaFuncSetAttribute(gemm_f16, cudaFuncAttributeMaxDynamicSharedMemorySize,
                         GEMM_SMEM);
    cudaFuncSetAttribute(flash_f16, cudaFuncAttributeMaxDynamicSharedMemorySize,
                         ATT_SMEM);

    // launches 0..2 = prep; launch 3 = QKV GEMM
    embed_bias_kernel<<<NROWS + 72, 256>>>(tokens, emb, x, xh, bqkv, bqs);  // 0
    prep_weights_a<<<dim3(4096, 1, 6), 256>>>(Wqkv, Wo, wt);                // 1
    prep_weights_b<<<dim3(4096, 1, 6), 256>>>(W1, W2, wt);                  // 2

    for (int l = 0; l < 6; ++l) {
        __half* wl = wt + (size_t)l * WT_LAYER;

        gemm_f16<<<dim3(3072 / 128, NROWS / 128), 256, GEMM_SMEM>>>(
            xh, wl + WT_QKV, bqs + (size_t)l * 3072, qkv,
            NROWS, 3 * DM, DM, 2);                                          // 3

        flash_f16<<<dim3(TSEQ / 128, 16, 4), 256, ATT_SMEM>>>(qkv, attn);

        gemm_f16<<<dim3(1024 / 128, NROWS / 128), 256, GEMM_SMEM>>>(
            attn, wl + WT_O, bo + (size_t)l * DM, proj,
            NROWS, DM, DM, 0);

        add_ln_kernel<<<NROWS, 256>>>(x, proj, g1 + (size_t)l * DM,
                                      be1 + (size_t)l * DM, x, xh);

        gemm_f16<<<dim3(2048 / 128, NROWS / 128), 256, GEMM_SMEM>>>(
            xh, wl + WT_W1, bf1 + (size_t)l * DFF, ff1,
            NROWS, DFF, DM, 3);

        gemm_f16<<<dim3(1024 / 128, NROWS / 128), 256, GEMM_SMEM>>>(
            ff1, wl + WT_W2, bf2 + (size_t)l * DM, ff2,
            NROWS, DM, DFF, 0);

        add_ln_kernel<<<NROWS, 256>>>(x, ff2, g2 + (size_t)l * DM,
                                      be2 + (size_t)l * DM,
                                      (l == 5) ? outp : x, xh);
    }
}

// round 13
// speedup vs baseline: 1.0868x; 1.0023x over previous
#include <cuda_runtime.h>
#include <cuda_fp16.h>
#include <math.h>
#include <stdint.h>

// Problem constants
#define NROWS 8192      // B*T
#define TSEQ  2048
#define DM    1024
#define DFF   2048

#define SCALE_QLOG2 0.18033688011112042f   // (1/sqrt(64)) * log2(e)

// ---------------- scratch (static device globals) ---------------------------
__device__ float  g_x   [NROWS * DM];
__device__ __half g_xh  [NROWS * DM];
__device__ __half g_qkv [NROWS * 3 * DM];
__device__ __half g_attn[NROWS * DM];
__device__ float  g_proj[NROWS * DM];
__device__ __half g_ff1 [NROWS * DFF];
__device__ float  g_ff2 [NROWS * DM];

#define WT_QKV 0
#define WT_O   (3072 * 1024)
#define WT_W1  (WT_O + 1024 * 1024)
#define WT_W2  (WT_W1 + 2048 * 1024)
#define WT_LAYER (WT_W2 + 1024 * 2048)
__device__ __half g_wt[6 * WT_LAYER];
__device__ float  g_bqs[6 * 3072];

// ---------------- PTX helpers ------------------------------------------------
__device__ __forceinline__ float ex2(float x) {
    float y; asm("ex2.approx.f32 %0, %1;" : "=f"(y) : "f"(x)); return y;
}
__device__ __forceinline__ uint32_t pack_half2(float lo, float hi) {
    uint32_t u;
    asm("cvt.rn.f16x2.f32 %0, %1, %2;" : "=r"(u) : "f"(hi), "f"(lo));
    return u;
}
__device__ __forceinline__ void mma_f16(
    float& d0, float& d1, float& d2, float& d3,
    uint32_t a0, uint32_t a1, uint32_t a2, uint32_t a3,
    uint32_t b0, uint32_t b1)
{
    asm volatile(
        "mma.sync.aligned.m16n8k16.row.col.f32.f16.f16.f32 "
        "{%0,%1,%2,%3},{%4,%5,%6,%7},{%8,%9},{%0,%1,%2,%3};\n"
        : "+f"(d0), "+f"(d1), "+f"(d2), "+f"(d3)
        : "r"(a0), "r"(a1), "r"(a2), "r"(a3), "r"(b0), "r"(b1));
}
__device__ __forceinline__ uint32_t smem_u32(const void* p) {
    uint32_t a;
    asm("{ .reg .u64 t; cvta.to.shared.u64 t, %1; cvt.u32.u64 %0, t; }"
        : "=r"(a) : "l"(p));
    return a;
}
#define LDSM4(R0, R1, R2, R3, ADDR) \
    asm volatile("ldmatrix.sync.aligned.m8n8.x4.shared.b16 {%0,%1,%2,%3}, [%4];" \
        : "=r"(R0), "=r"(R1), "=r"(R2), "=r"(R3) : "r"(ADDR))
#define LDSM4T(R0, R1, R2, R3, ADDR) \
    asm volatile("ldmatrix.sync.aligned.m8n8.x4.trans.shared.b16 {%0,%1,%2,%3}, [%4];" \
        : "=r"(R0), "=r"(R1), "=r"(R2), "=r"(R3) : "r"(ADDR))
#define CPA16(dst, src) \
    asm volatile("cp.async.ca.shared.global [%0], [%1], 16;" \
        :: "r"(dst), "l"(src) : "memory")
#define CPA_COMMIT() asm volatile("cp.async.commit_group;" ::: "memory")
#define CPA_WAIT1()  asm volatile("cp.async.wait_group 1;" ::: "memory")
#define CPA_WAIT2()  asm volatile("cp.async.wait_group 2;" ::: "memory")
#define CPA_WAIT3()  asm volatile("cp.async.wait_group 3;" ::: "memory")

// ---------------- weight prep ------------------------------------------------
__device__ __forceinline__ void transpose_tile(
    const float* __restrict__ W, __half* __restrict__ WT, int K, int N,
    int bx, int by, int scale_rows, float scale)
{
    __shared__ float t[32][33];
    int tx = threadIdx.x & 31, ty = threadIdx.x >> 5;
    #pragma unroll
    for (int i = 0; i < 4; i++)
        t[ty + i * 8][tx] = W[(size_t)(by * 32 + ty + i * 8) * N + bx * 32 + tx];
    __syncthreads();
    #pragma unroll
    for (int i = 0; i < 4; i++) {
        int n = bx * 32 + ty + i * 8;
        float v = t[tx][ty + i * 8];
        if (n < scale_rows) v *= scale;
        WT[(size_t)n * K + by * 32 + tx] = __float2half_rn(v);
    }
}

__global__ __launch_bounds__(256) void prep_weights_a(
    const float* __restrict__ Wqkv, const float* __restrict__ Wo,
    __half* __restrict__ wt)
{
    int l = blockIdx.z;
    __half* wl = wt + (size_t)l * WT_LAYER;
    int bid = blockIdx.x;                       // 4096 = 3072 QKV + 1024 O
    if (bid < 3072) {
        transpose_tile(Wqkv + (size_t)l * 1024 * 3072, wl + WT_QKV,
                       1024, 3072, bid % 96, bid / 96, 1024, SCALE_QLOG2);
    } else {
        bid -= 3072;
        transpose_tile(Wo + (size_t)l * 1024 * 1024, wl + WT_O,
                       1024, 1024, bid % 32, bid / 32, 0, 1.f);
    }
}

__global__ __launch_bounds__(256) void prep_weights_b(
    const float* __restrict__ W1, const float* __restrict__ W2,
    __half* __restrict__ wt)
{
    int l = blockIdx.z;
    __half* wl = wt + (size_t)l * WT_LAYER;
    int bid = blockIdx.x;                       // 4096 = 2048 W1 + 2048 W2
    if (bid < 2048) {
        transpose_tile(W1 + (size_t)l * 1024 * 2048, wl + WT_W1,
                       1024, 2048, bid % 64, bid / 64, 0, 1.f);
    } else {
        bid -= 2048;
        transpose_tile(W2 + (size_t)l * 2048 * 1024, wl + WT_W2,
                       2048, 1024, bid % 32, bid / 32, 0, 1.f);
    }
}

// ---------------- embedding + PE + qkv bias scaling -------------------------
__global__ __launch_bounds__(256) void embed_bias_kernel(
    const int* __restrict__ tokens, const float* __restrict__ emb,
    float* __restrict__ x, __half* __restrict__ xh,
    const float* __restrict__ bqkv, float* __restrict__ bqs)
{
    if (blockIdx.x >= NROWS) {
        int i = (blockIdx.x - NROWS) * 256 + threadIdx.x;
        float v = bqkv[i];
        bqs[i] = ((i % 3072) < 1024) ? v * SCALE_QLOG2 : v;
        return;
    }
    int row = blockIdx.x;
    int tok = tokens[row];
    float tpos = (float)(row & (TSEQ - 1));
    int c = threadIdx.x * 4;
    float4 e = *(const float4*)(emb + (size_t)tok * DM + c);
    float o[4] = {e.x, e.y, e.z, e.w};
    #pragma unroll
    for (int q = 0; q < 4; q++) {
        int cc = c + q;
        float fi = (float)(cc & ~1);
        float ang = tpos * __expf(fi * -0.00899447301950799f);
        o[q] += (cc & 1) ? cosf(ang) : sinf(ang);
    }
    float4 r; r.x = o[0]; r.y = o[1]; r.z = o[2]; r.w = o[3];
    *(float4*)(x + (size_t)row * DM + c) = r;
    uint2 u; u.x = pack_half2(o[0], o[1]); u.y = pack_half2(o[2], o[3]);
    *(uint2*)(xh + (size_t)row * DM + c) = u;
}

// ---------------- fp16 HMMA GEMM: 128x128 tile, 3-ring, 2 CTAs/SM -----------
#define GAST 72
#define STG_H (256 * GAST)
#define GEMM_SMEM (3 * STG_H * 2)

__global__ __launch_bounds__(256, 2) void gemm_f16(
    const __half* __restrict__ A, const __half* __restrict__ B,
    const float* __restrict__ bias, void* __restrict__ Cout,
    int M, int N, int K, int mode)
{
    extern __shared__ __half sh[];
    uint32_t sbase = smem_u32(sh);
    int tid = threadIdx.x, w = tid >> 5, lane = tid & 31;
    int g = lane >> 2, t = lane & 3;
    int wm = w >> 2, wn = w & 3;
    int rowBase = blockIdx.y * 128, colBase = blockIdx.x * 128;

    float acc[4][4][4];
    #pragma unroll
    for (int i = 0; i < 4; i++)
        #pragma unroll
        for (int j = 0; j < 4; j++)
            #pragma unroll
            for (int r = 0; r < 4; r++) acc[i][j][r] = 0.f;

    const int nc = K >> 6;

    #pragma unroll
    for (int c0 = 0; c0 < 2; ++c0) {
        uint32_t st = sbase + (uint32_t)c0 * (STG_H * 2);
        int kb = c0 * 64;
        #pragma unroll
        for (int it = 0; it < 4; ++it) {
            int p = tid + it * 256;
            int r = p >> 3, c8 = (p & 7) * 8;
            CPA16(st + (uint32_t)(r * GAST + c8) * 2u,
                  A + (size_t)(rowBase + r) * K + kb + c8);
            CPA16(st + (uint32_t)((128 + r) * GAST + c8) * 2u,
                  B + (size_t)(colBase + r) * K + kb + c8);
        }
        CPA_COMMIT();
    }

    int lm = lane & 15, lh8 = ((lane >> 4) & 1) * 8;
    int bn = (lane & 7) + (((lane >> 4) & 1) * 8);
    int bk8 = ((lane >> 3) & 1) * 8;

    for (int c = 0; c < nc; ++c) {
        CPA_WAIT1();
        __syncthreads();

        int cn = c + 2;
        if (cn < nc) {
            uint32_t s2 = sbase + (uint32_t)(cn % 3) * (STG_H * 2);
            int kb = cn * 64;
            #pragma unroll
            for (int it = 0; it < 4; ++it) {
                int p = tid + it * 256;
                int r = p >> 3, c8 = (p & 7) * 8;
                CPA16(s2 + (uint32_t)(r * GAST + c8) * 2u,
                      A + (size_t)(rowBase + r) * K + kb + c8);
                CPA16(s2 + (uint32_t)((128 + r) * GAST + c8) * 2u,
                      B + (size_t)(colBase + r) * K + kb + c8);
            }
        }
        CPA_COMMIT();

        uint32_t st = sbase + (uint32_t)(c % 3) * (STG_H * 2);
        uint32_t aB = st, bB = st + 128 * GAST * 2;

        #pragma unroll
        for (int ks = 0; ks < 4; ++ks) {
            uint32_t af[4][4], bf[4][2];
            #pragma unroll
            for (int mt = 0; mt < 4; ++mt) {
                int m0 = wm * 64 + mt * 16;
                uint32_t ad = aB + (uint32_t)((m0 + lm) * GAST + ks * 16 + lh8) * 2u;
                LDSM4(af[mt][0], af[mt][1], af[mt][2], af[mt][3], ad);
            }
            #pragma unroll
            for (int j = 0; j < 2; ++j) {
                int n0 = wn * 32 + j * 16;
                uint32_t bd = bB + (uint32_t)((n0 + bn) * GAST + ks * 16 + bk8) * 2u;
                LDSM4(bf[2*j][0], bf[2*j][1], bf[2*j+1][0], bf[2*j+1][1], bd);
            }
            #pragma unroll
            for (int mt = 0; mt < 4; ++mt)
                #pragma unroll
                for (int nt = 0; nt < 4; ++nt)
                    mma_f16(acc[mt][nt][0], acc[mt][nt][1],
                            acc[mt][nt][2], acc[mt][nt][3],
                            af[mt][0], af[mt][1], af[mt][2], af[mt][3],
                            bf[nt][0], bf[nt][1]);
        }
    }

    int relu = mode & 1, hout = mode & 2;
    #pragma unroll
    for (int mt = 0; mt < 4; ++mt) {
        int r0g = rowBase + wm * 64 + mt * 16 + g;
        #pragma unroll
        for (int nt = 0; nt < 4; ++nt) {
            int cc = colBase + wn * 32 + nt * 8 + 2 * t;
            float b0 = bias[cc], b1 = bias[cc + 1];
            float v0 = acc[mt][nt][0] + b0, v1 = acc[mt][nt][1] + b1;
            float v2 = acc[mt][nt][2] + b0, v3 = acc[mt][nt][3] + b1;
            if (relu) {
                v0 = fmaxf(v0, 0.f); v1 = fmaxf(v1, 0.f);
                v2 = fmaxf(v2, 0.f); v3 = fmaxf(v3, 0.f);
            }
            if (hout) {
                *(uint32_t*)((__half*)Cout + (size_t)r0g * N + cc) = pack_half2(v0, v1);
                *(uint32_t*)((__half*)Cout + (size_t)(r0g + 8) * N + cc) = pack_half2(v2, v3);
            } else {
                float2 p0; p0.x = v0; p0.y = v1;
                float2 p1; p1.x = v2; p1.y = v3;
                *(float2*)((float*)Cout + (size_t)r0g * N + cc) = p0;
                *(float2*)((float*)Cout + (size_t)(r0g + 8) * N + cc) = p1;
            }
        }
    }
}

// ---------------- fp16 flash attention: exact online softmax ----------------
#define FQST 72
#define FKST 72
#define FQ_OFF 0
#define FKBUF  (64 * FKST)
#define FK_OFF (128 * FQST)
#define FV_OFF (FK_OFF + 4 * FKBUF)
#define ATT_SMEM ((FV_OFF + 4 * FKBUF) * 2)
#define NTILE (TSEQ / 64)

__global__ __launch_bounds__(256, 2) void flash_f16(
    const __half* __restrict__ qkv, __half* __restrict__ attn)
{
    extern __shared__ __half sf[];
    uint32_t sbase = smem_u32(sf);
    int tid = threadIdx.x, w = tid >> 5, lane = tid & 31;
    int g = lane >> 2, t = lane & 3;
    int h = blockIdx.y, b = blockIdx.z;
    int btQ = b * TSEQ + blockIdx.x * 128;
    int rl0 = w * 16;
    int lm = lane & 15, lh8 = ((lane >> 4) & 1) * 8;
    int bn = (lane & 7) + (((lane >> 4) & 1) * 8);
    int bk8 = ((lane >> 3) & 1) * 8;

    #pragma unroll
    for (int it = 0; it < 4; ++it) {
        int p = tid + it * 256;
        int r = p >> 3, c8 = (p & 7) * 8;
        CPA16(sbase + (uint32_t)(FQ_OFF + r * FQST + c8) * 2u,
              qkv + (size_t)(btQ + r) * 3072 + h * 64 + c8);
    }
    CPA_COMMIT();

    #pragma unroll
    for (int i0 = 0; i0 < 3; ++i0) {
        #pragma unroll
        for (int it = 0; it < 2; ++it) {
            int p = tid + it * 256;
            int r = p >> 3, c8 = (p & 7) * 8;
            const __half* src = qkv + (size_t)(b * TSEQ + i0 * 64 + r) * 3072 + h * 64;
            CPA16(sbase + (uint32_t)(FK_OFF + i0 * FKBUF + r * FKST + c8) * 2u,
                  src + 1024 + c8);
            CPA16(sbase + (uint32_t)(FV_OFF + i0 * FKBUF + r * FKST + c8) * 2u,
                  src + 2048 + c8);
        }
        CPA_COMMIT();
    }

    CPA_WAIT3();
    __syncthreads();

    float o[8][4];
    #pragma unroll
    for (int d = 0; d < 8; d++)
        #pragma unroll
        for (int r = 0; r < 4; r++) o[d][r] = 0.f;
    float m0 = -1e30f, m1 = -1e30f;
    float l0p = 0.f, l1p = 0.f;

    for (int c = 0; c < NTILE; ++c) {
        CPA_WAIT2();
        __syncthreads();

        int cn = c + 3;
        if (cn < NTILE) {
            int rb = cn & 3;
            #pragma unroll
            for (int it = 0; it < 2; ++it) {
                int p = tid + it * 256;
                int r = p >> 3, c8 = (p & 7) * 8;
                const __half* src = qkv + (size_t)(b * TSEQ + cn * 64 + r) * 3072 + h * 64;
                CPA16(sbase + (uint32_t)(FK_OFF + rb * FKBUF + r * FKST + c8) * 2u,
                      src + 1024 + c8);
                CPA16(sbase + (uint32_t)(FV_OFF + rb * FKBUF + r * FKST + c8) * 2u,
                      src + 2048 + c8);
            }
        }
        CPA_COMMIT();

        uint32_t kB = sbase + (uint32_t)(FK_OFF + (c & 3) * FKBUF) * 2u;
        uint32_t vB = sbase + (uint32_t)(FV_OFF + (c & 3) * FKBUF) * 2u;

        float s[8][4];
        #pragma unroll
        for (int nt = 0; nt < 8; ++nt)
            s[nt][0] = s[nt][1] = s[nt][2] = s[nt][3] = 0.f;
        #pragma unroll
        for (int ks = 0; ks < 4; ++ks) {
            uint32_t qa[4];
            uint32_t qd = sbase + (uint32_t)(FQ_OFF + (rl0 + lm) * FQST + ks * 16 + lh8) * 2u;
            LDSM4(qa[0], qa[1], qa[2], qa[3], qd);
            uint32_t kf[8][2];
            #pragma unroll
            for (int j = 0; j < 4; ++j) {
                uint32_t kd = kB + (uint32_t)((j * 16 + bn) * FKST + ks * 16 + bk8) * 2u;
                LDSM4(kf[2*j][0], kf[2*j][1], kf[2*j+1][0], kf[2*j+1][1], kd);
            }
            #pragma unroll
            for (int nt = 0; nt < 8; ++nt)
                mma_f16(s[nt][0], s[nt][1], s[nt][2], s[nt][3],
                        qa[0], qa[1], qa[2], qa[3], kf[nt][0], kf[nt][1]);
        }

        float mx0 = -1e30f, mx1 = -1e30f;
        #pragma unroll
        for (int nt = 0; nt < 8; ++nt) {
            mx0 = fmaxf(mx0, fmaxf(s[nt][0], s[nt][1]));
            mx1 = fmaxf(mx1, fmaxf(s[nt][2], s[nt][3]));
        }
        mx0 = fmaxf(mx0, __shfl_xor_sync(0xffffffffu, mx0, 1));
        mx0 = fmaxf(mx0, __shfl_xor_sync(0xffffffffu, mx0, 2));
        mx1 = fmaxf(mx1, __shfl_xor_sync(0xffffffffu, mx1, 1));
        mx1 = fmaxf(mx1, __shfl_xor_sync(0xffffffffu, mx1, 2));
        float nm0 = fmaxf(m0, mx0), nm1 = fmaxf(m1, mx1);
        float al0 = ex2(m0 - nm0), al1 = ex2(m1 - nm1);
        m0 = nm0; m1 = nm1;

        uint32_t pa[4][4];
        float rs0 = 0.f, rs1 = 0.f;
        #pragma unroll
        for (int j = 0; j < 4; ++j) {
            float p00 = ex2(s[2*j][0] - m0),   p01 = ex2(s[2*j][1] - m0);
            float p02 = ex2(s[2*j][2] - m1),   p03 = ex2(s[2*j][3] - m1);
            float p10 = ex2(s[2*j+1][0] - m0), p11 = ex2(s[2*j+1][1] - m0);
            float p12 = ex2(s[2*j+1][2] - m1), p13 = ex2(s[2*j+1][3] - m1);
            rs0 += p00 + p01 + p10 + p11;
            rs1 += p02 + p03 + p12 + p13;
            pa[j][0] = pack_half2(p00, p01);
            pa[j][1] = pack_half2(p02, p03);
            pa[j][2] = pack_half2(p10, p11);
            pa[j][3] = pack_half2(p12, p13);
        }
        l0p = l0p * al0 + rs0;
        l1p = l1p * al1 + rs1;
        #pragma unroll
        for (int d = 0; d < 8; d++) {
            o[d][0] *= al0; o[d][1] *= al0;
            o[d][2] *= al1; o[d][3] *= al1;
        }

        #pragma unroll
        for (int ks = 0; ks < 4; ++ks) {
            uint32_t vf[8][2];
            #pragma unroll
            for (int j = 0; j < 4; ++j) {
                uint32_t vd = vB + (uint32_t)((ks * 16 + lm) * FKST + j * 16 + lh8) * 2u;
                LDSM4T(vf[2*j][0], vf[2*j][1], vf[2*j+1][0], vf[2*j+1][1], vd);
            }
            #pragma unroll
            for (int dt = 0; dt < 8; ++dt)
                mma_f16(o[dt][0], o[dt][1], o[dt][2], o[dt][3],
                        pa[ks][0], pa[ks][1], pa[ks][2], pa[ks][3],
                        vf[dt][0], vf[dt][1]);
        }
    }

    l0p += __shfl_xor_sync(0xffffffffu, l0p, 1);
    l0p += __shfl_xor_sync(0xffffffffu, l0p, 2);
    l1p += __shfl_xor_sync(0xffffffffu, l1p, 1);
    l1p += __shfl_xor_sync(0xffffffffu, l1p, 2);

    float i0 = 1.f / l0p, i1 = 1.f / l1p;
    #pragma unroll
    for (int dt = 0; dt < 8; ++dt) {
        size_t base = (size_t)(btQ + rl0 + g) * DM + h * 64 + dt * 8 + 2 * t;
        *(uint32_t*)(attn + base) = pack_half2(o[dt][0] * i0, o[dt][1] * i0);
        *(uint32_t*)(attn + base + 8 * DM) = pack_half2(o[dt][2] * i1, o[dt][3] * i1);
    }
}

// ---------------- fused residual add + LayerNorm (single-pass moments) ------
// var = E[x^2] - mean^2 (safe: LN-input variance is O(1), no cancellation).
__global__ __launch_bounds__(256) void add_ln_kernel(
    const float* __restrict__ x, const float* __restrict__ y,
    const float* __restrict__ g, const float* __restrict__ b,
    float* __restrict__ outp, __half* __restrict__ oh)
{
    __shared__ float redS[8], redQ[8];
    __shared__ float bcS, bcQ;
    int row = blockIdx.x, tid = threadIdx.x;
    int lane = tid & 31, warp = tid >> 5;

    float4 xv = *(const float4*)(x + (size_t)row * DM + tid * 4);
    float4 yv = *(const float4*)(y + (size_t)row * DM + tid * 4);
    float v0 = xv.x + yv.x, v1 = xv.y + yv.y, v2 = xv.z + yv.z, v3 = xv.w + yv.w;

    float s  = v0 + v1 + v2 + v3;
    float sq = v0 * v0 + v1 * v1 + v2 * v2 + v3 * v3;
    #pragma unroll
    for (int off = 16; off > 0; off >>= 1) {
        s  += __shfl_xor_sync(0xffffffffu, s,  off);
        sq += __shfl_xor_sync(0xffffffffu, sq, off);
    }
    if (lane == 0) { redS[warp] = s; redQ[warp] = sq; }
    __syncthreads();
    if (tid < 8) {
        float ts = redS[tid], tq = redQ[tid];
        #pragma unroll
        for (int off = 4; off > 0; off >>= 1) {
            ts += __shfl_xor_sync(0xffu, ts, off);
            tq += __shfl_xor_sync(0xffu, tq, off);
        }
        if (tid == 0) { bcS = ts; bcQ = tq; }
    }
    __syncthreads();
    float mean = bcS * (1.f / (float)DM);
    float var  = bcQ * (1.f / (float)DM) - mean * mean;
    float rstd = rsqrtf(var + 1e-5f);

    float d0 = v0 - mean, d1 = v1 - mean, d2 = v2 - mean, d3 = v3 - mean;
    float4 gv = *(const float4*)(g + tid * 4);
    float4 bv = *(const float4*)(b + tid * 4);
    float4 ov;
    ov.x = d0 * rstd * gv.x + bv.x;
    ov.y = d1 * rstd * gv.y + bv.y;
    ov.z = d2 * rstd * gv.z + bv.z;
    ov.w = d3 * rstd * gv.w + bv.w;
    *(float4*)(outp + (size_t)row * DM + tid * 4) = ov;
    uint2 u; u.x = pack_half2(ov.x, ov.y); u.y = pack_half2(ov.z, ov.w);
    *(uint2*)(oh + (size_t)row * DM + tid * 4) = u;
}

// ---------------- launcher ---------------------------------------------------
extern "C" void kernel_launch(void* const* d_in, const int* in_sizes, int n_in,
                              void* d_out, int out_size)
{
    (void)in_sizes; (void)n_in; (void)out_size;
    const int*   tokens = (const int*)  d_in[0];
    const float* emb  = (const float*)d_in[1];
    const float* Wqkv = (const float*)d_in[2];
    const float* bqkv = (const float*)d_in[3];
    const float* Wo   = (const float*)d_in[4];
    const float* bo   = (const float*)d_in[5];
    const float* g1   = (const float*)d_in[6];
    const float* be1  = (const float*)d_in[7];
    const float* W1   = (const float*)d_in[8];
    const float* bf1  = (const float*)d_in[9];
    const float* W2   = (const float*)d_in[10];
    const float* bf2  = (const float*)d_in[11];
    const float* g2   = (const float*)d_in[12];
    const float* be2  = (const float*)d_in[13];
    float* outp = (float*)d_out;

    float *x, *proj, *ff2, *bqs;
    __half *xh, *qkv, *attn, *ff1, *wt;
    cudaGetSymbolAddress((void**)&x,    g_x);
    cudaGetSymbolAddress((void**)&xh,   g_xh);
    cudaGetSymbolAddress((void**)&qkv,  g_qkv);
    cudaGetSymbolAddress((void**)&attn, g_attn);
    cudaGetSymbolAddress((void**)&proj, g_proj);
    cudaGetSymbolAddress((void**)&ff1,  g_ff1);
    cudaGetSymbolAddress((void**)&ff2,  g_ff2);
    cudaGetSymbolAddress((void**)&wt,   g_wt);
    cudaGetSymbolAddress((void**)&bqs,  g_bqs);

    cudaFuncSetAttribute(gemm_f16, cudaFuncAttributeMaxDynamicSharedMemorySize,
                         GEMM_SMEM);
    cudaFuncSetAttribute(flash_f16, cudaFuncAttributeMaxDynamicSharedMemorySize,
                         ATT_SMEM);

    embed_bias_kernel<<<NROWS + 72, 256>>>(tokens, emb, x, xh, bqkv, bqs);  // 0
    prep_weights_a<<<dim3(4096, 1, 6), 256>>>(Wqkv, Wo, wt);                // 1
    prep_weights_b<<<dim3(4096, 1, 6), 256>>>(W1, W2, wt);                  // 2

    for (int l = 0; l < 6; ++l) {
        __half* wl = wt + (size_t)l * WT_LAYER;

        gemm_f16<<<dim3(3072 / 128, NROWS / 128), 256, GEMM_SMEM>>>(
            xh, wl + WT_QKV, bqs + (size_t)l * 3072, qkv,
            NROWS, 3 * DM, DM, 2);                                          // 3

        flash_f16<<<dim3(TSEQ / 128, 16, 4), 256, ATT_SMEM>>>(qkv, attn);

        gemm_f16<<<dim3(1024 / 128, NROWS / 128), 256, GEMM_SMEM>>>(
            attn, wl + WT_O, bo + (size_t)l * DM, proj,
            NROWS, DM, DM, 0);

        add_ln_kernel<<<NROWS, 256>>>(x, proj, g1 + (size_t)l * DM,
                                      be1 + (size_t)l * DM, x, xh);

        gemm_f16<<<dim3(2048 / 128, NROWS / 128), 256, GEMM_SMEM>>>(
            xh, wl + WT_W1, bf1 + (size_t)l * DFF, ff1,
            NROWS, DFF, DM, 3);

        gemm_f16<<<dim3(1024 / 128, NROWS / 128), 256, GEMM_SMEM>>>(
            ff1, wl + WT_W2, bf2 + (size_t)l * DM, ff2,
            NROWS, DM, DFF, 0);

        add_ln_kernel<<<NROWS, 256>>>(x, ff2, g2 + (size_t)l * DM,
                                      be2 + (size_t)l * DM,
                                      (l == 5) ? outp : x, xh);
    }
}